// round 4
// baseline (speedup 1.0000x reference)
#include <cuda_runtime.h>
#include <math.h>

#define NLAYER 8
#define H 1024
#define NH 16
#define NKV 8
#define HD 128
#define FFI 3072
#define VOC 32000
#define BATCH 2
#define SEQ 1024
#define T (BATCH*SEQ)

// ------------------------- scratch (device globals; no allocs) -------------------------
__device__ float g_h[T*H];                                   // residual stream  (8 MB)
__device__ float g_x[T*H];                                   // normed activations
__device__ float g_q[T*NH*HD];                               // 16 MB
__device__ float g_k[T*NKV*HD];                               // 8 MB
__device__ float g_v[T*NKV*HD];                               // 8 MB
__device__ float g_sc[(size_t)BATCH*NH*SEQ*SEQ];             // 134 MB scores/probs
__device__ float g_ctx[T*NH*HD];                              // 16 MB
__device__ float g_gate[T*FFI];                               // 24 MB
__device__ float g_up[T*FFI];                                 // 24 MB
__device__ float g_cos[SEQ*64];
__device__ float g_sin[SEQ*64];

// ------------------------- rope tables (double precision once) -------------------------
__global__ void rope_table_kernel() {
    int pos = blockIdx.x;
    int j = threadIdx.x;                       // 0..63
    double inv = pow(1.0e6, -((double)(2 * j)) / 128.0);
    double ang = (double)pos * inv;
    g_cos[pos * 64 + j] = (float)cos(ang);
    g_sin[pos * 64 + j] = (float)sin(ang);
}

// ------------------------- embedding gather -------------------------
__global__ void embed_kernel(const int* __restrict__ ids, const float* __restrict__ emb,
                             float* __restrict__ out) {
    int t = blockIdx.x;
    int id = ids[t];
    const float4* src = (const float4*)(emb + (size_t)id * H);
    float4* dst = (float4*)(out + (size_t)t * H);
    dst[threadIdx.x] = src[threadIdx.x];       // 256 threads * float4 = 1024 floats
}

// ------------------------- rmsnorm over H=1024 -------------------------
__global__ __launch_bounds__(256) void rmsnorm_kernel(const float* __restrict__ in,
                                                      const float* __restrict__ w,
                                                      float* __restrict__ out) {
    int r = blockIdx.x, tid = threadIdx.x;
    const float4* ip = (const float4*)(in + (size_t)r * H);
    float4 v = ip[tid];
    float sq = v.x*v.x + v.y*v.y + v.z*v.z + v.w*v.w;
    __shared__ float red[8];
    __shared__ float s_scale;
    #pragma unroll
    for (int o = 16; o > 0; o >>= 1) sq += __shfl_xor_sync(0xffffffffu, sq, o);
    if ((tid & 31) == 0) red[tid >> 5] = sq;
    __syncthreads();
    if (tid == 0) {
        float t2 = 0.f;
        #pragma unroll
        for (int i = 0; i < 8; i++) t2 += red[i];
        s_scale = rsqrtf(t2 * (1.0f / H) + 1e-6f);
    }
    __syncthreads();
    float sc = s_scale;
    float4 wv = ((const float4*)w)[tid];
    float4 o;
    o.x = v.x * sc * wv.x; o.y = v.y * sc * wv.y;
    o.z = v.z * sc * wv.z; o.w = v.w * sc * wv.w;
    ((float4*)(out + (size_t)r * H))[tid] = o;
}

// ------------------------- per-head rmsnorm + rope (in place) -------------------------
__global__ __launch_bounds__(HD) void qknorm_rope_kernel(float* __restrict__ x,
                                                         const float* __restrict__ w,
                                                         int nheads) {
    int t = blockIdx.x;                 // token 0..T-1
    int hh = blockIdx.y;
    int d = threadIdx.x;                // 0..127
    float* p = x + ((size_t)t * nheads + hh) * HD;
    float val = p[d];
    float sq = val * val;
    #pragma unroll
    for (int o = 16; o > 0; o >>= 1) sq += __shfl_xor_sync(0xffffffffu, sq, o);
    __shared__ float red[4];
    __shared__ float sh[HD];
    if ((d & 31) == 0) red[d >> 5] = sq;
    __syncthreads();
    float tot = red[0] + red[1] + red[2] + red[3];
    float rms = rsqrtf(tot * (1.0f / HD) + 1e-6f);
    float xn = val * rms * w[d];
    sh[d] = xn;
    __syncthreads();
    int pos = t & (SEQ - 1);
    int j = d & 63;
    float c = g_cos[pos * 64 + j];
    float s = g_sin[pos * 64 + j];
    float out = (d < 64) ? (xn * c - sh[d + 64] * s)
                         : (xn * c + sh[d - 64] * s);
    p[d] = out;
}

// ------------------------- generic SGEMM: C (+)= A[MxK] @ B[KxN], row-major -------------------------
__global__ __launch_bounds__(256) void sgemm_nn(const float* __restrict__ A,
                                                const float* __restrict__ B,
                                                float* __restrict__ C,
                                                int M, int N, int K, int accum) {
    __shared__ float As[8][128];
    __shared__ float Bs[8][128];
    int tid = threadIdx.x;
    int bm = blockIdx.y * 128, bn = blockIdx.x * 128;
    int arow = tid >> 1;                // 0..127
    int acol = (tid & 1) * 4;           // 0 or 4
    int brow = tid >> 5;                // 0..7
    int bcol = (tid & 31) * 4;          // 0..124
    const float* Aptr = A + (size_t)(bm + arow) * K + acol;
    const float* Bptr = B + (size_t)brow * N + bn + bcol;
    int ty = tid >> 4, tx = tid & 15;
    float acc[8][8];
    #pragma unroll
    for (int i = 0; i < 8; i++)
        #pragma unroll
        for (int j = 0; j < 8; j++) acc[i][j] = 0.f;

    for (int k0 = 0; k0 < K; k0 += 8) {
        float4 av = *(const float4*)(Aptr + k0);
        float4 bv = *(const float4*)(Bptr + (size_t)k0 * N);
        As[acol + 0][arow] = av.x; As[acol + 1][arow] = av.y;
        As[acol + 2][arow] = av.z; As[acol + 3][arow] = av.w;
        *(float4*)&Bs[brow][bcol] = bv;
        __syncthreads();
        #pragma unroll
        for (int k = 0; k < 8; k++) {
            float a[8], b[8];
            #pragma unroll
            for (int i = 0; i < 8; i++) a[i] = As[k][ty * 8 + i];
            #pragma unroll
            for (int j = 0; j < 8; j++) b[j] = Bs[k][tx * 8 + j];
            #pragma unroll
            for (int i = 0; i < 8; i++)
                #pragma unroll
                for (int j = 0; j < 8; j++)
                    acc[i][j] = fmaf(a[i], b[j], acc[i][j]);
        }
        __syncthreads();
    }
    #pragma unroll
    for (int i = 0; i < 8; i++) {
        float* Cp = C + (size_t)(bm + ty * 8 + i) * N + bn + tx * 8;
        #pragma unroll
        for (int j = 0; j < 8; j += 4) {
            float4 vout;
            if (accum) {
                float4 cv = *(const float4*)(Cp + j);
                vout.x = cv.x + acc[i][j + 0]; vout.y = cv.y + acc[i][j + 1];
                vout.z = cv.z + acc[i][j + 2]; vout.w = cv.w + acc[i][j + 3];
            } else {
                vout.x = acc[i][j + 0]; vout.y = acc[i][j + 1];
                vout.z = acc[i][j + 2]; vout.w = acc[i][j + 3];
            }
            *(float4*)(Cp + j) = vout;
        }
    }
}

// ------------------------- attention scores: S[z,i,j] = scale * q_i . k_j (NT) -------------------------
__global__ __launch_bounds__(256) void attn_scores_kernel(const float* __restrict__ q,
                                                          const float* __restrict__ k,
                                                          float* __restrict__ sc) {
    int z = blockIdx.z;                 // b*NH + h
    int b = z >> 4, h = z & 15;
    int i0 = blockIdx.y * 64, j0 = blockIdx.x * 64;
    if (j0 > i0 + 63) return;           // strictly-upper tile: never read by softmax
    const float* qb = q + ((size_t)b * SEQ * NH + h) * HD;
    const float* kb = k + ((size_t)b * SEQ * NKV + (h >> 1)) * HD;
    __shared__ float Qs[16][64];
    __shared__ float Ks[16][64];
    int tid = threadIdx.x;
    int lrow = tid >> 2;                // 0..63
    int lcol = (tid & 3) * 4;           // 0,4,8,12
    int ty = tid >> 4, tx = tid & 15;
    float acc[4][4];
    #pragma unroll
    for (int i = 0; i < 4; i++)
        #pragma unroll
        for (int j = 0; j < 4; j++) acc[i][j] = 0.f;

    for (int d0 = 0; d0 < HD; d0 += 16) {
        float4 qv = *(const float4*)(qb + (size_t)(i0 + lrow) * (NH * HD) + d0 + lcol);
        float4 kv = *(const float4*)(kb + (size_t)(j0 + lrow) * (NKV * HD) + d0 + lcol);
        Qs[lcol + 0][lrow] = qv.x; Qs[lcol + 1][lrow] = qv.y;
        Qs[lcol + 2][lrow] = qv.z; Qs[lcol + 3][lrow] = qv.w;
        Ks[lcol + 0][lrow] = kv.x; Ks[lcol + 1][lrow] = kv.y;
        Ks[lcol + 2][lrow] = kv.z; Ks[lcol + 3][lrow] = kv.w;
        __syncthreads();
        #pragma unroll
        for (int d = 0; d < 16; d++) {
            float a[4], bb[4];
            #pragma unroll
            for (int i = 0; i < 4; i++) a[i] = Qs[d][ty * 4 + i];
            #pragma unroll
            for (int j = 0; j < 4; j++) bb[j] = Ks[d][tx * 4 + j];
            #pragma unroll
            for (int i = 0; i < 4; i++)
                #pragma unroll
                for (int j = 0; j < 4; j++)
                    acc[i][j] = fmaf(a[i], bb[j], acc[i][j]);
        }
        __syncthreads();
    }
    const float scale = 0.08838834764831845f;   // 1/sqrt(128)
    size_t zoff = (size_t)z * SEQ * SEQ;
    #pragma unroll
    for (int i = 0; i < 4; i++)
        #pragma unroll
        for (int j = 0; j < 4; j++)
            sc[zoff + (size_t)(i0 + ty * 4 + i) * SEQ + j0 + tx * 4 + j] = acc[i][j] * scale;
}

// ------------------------- causal softmax, row-wise (in place) -------------------------
__global__ __launch_bounds__(256) void softmax_kernel(float* __restrict__ sc) {
    int i = blockIdx.x;
    int z = blockIdx.y;
    float* row = sc + (size_t)z * SEQ * SEQ + (size_t)i * SEQ;
    int len = i + 1;
    int tid = threadIdx.x;
    __shared__ float red[8];
    float m = -1e30f;
    for (int j = tid; j < len; j += 256) m = fmaxf(m, row[j]);
    #pragma unroll
    for (int o = 16; o > 0; o >>= 1) m = fmaxf(m, __shfl_xor_sync(0xffffffffu, m, o));
    if ((tid & 31) == 0) red[tid >> 5] = m;
    __syncthreads();
    if (tid == 0) {
        float t = red[0];
        #pragma unroll
        for (int w = 1; w < 8; w++) t = fmaxf(t, red[w]);
        red[0] = t;
    }
    __syncthreads();
    float bm = red[0];
    __syncthreads();
    float s = 0.f;
    for (int j = tid; j < len; j += 256) s += __expf(row[j] - bm);
    #pragma unroll
    for (int o = 16; o > 0; o >>= 1) s += __shfl_xor_sync(0xffffffffu, s, o);
    if ((tid & 31) == 0) red[tid >> 5] = s;
    __syncthreads();
    if (tid == 0) {
        float t = 0.f;
        #pragma unroll
        for (int w = 0; w < 8; w++) t += red[w];
        red[0] = 1.0f / t;
    }
    __syncthreads();
    float inv = red[0];
    for (int j = tid; j < SEQ; j += 256)
        row[j] = (j < len) ? __expf(row[j] - bm) * inv : 0.f;
}

// ------------------------- ctx: C[i,:] = sum_j P[i,j] * V[j,:]  (NN, K-loop stops at diagonal) -------------------------
__global__ __launch_bounds__(256) void attn_ctx_kernel(const float* __restrict__ P,
                                                       const float* __restrict__ v,
                                                       float* __restrict__ ctx) {
    int z = blockIdx.y;                 // b*NH + h
    int b = z >> 4, h = z & 15;
    int i0 = blockIdx.x * 64;
    const float* Pb = P + (size_t)z * SEQ * SEQ;
    const float* vb = v + ((size_t)b * SEQ * NKV + (h >> 1)) * HD;
    __shared__ float Ps[16][64];
    __shared__ float Vs[16][128];
    int tid = threadIdx.x;
    int prow = tid >> 2, pcol = (tid & 3) * 4;     // 64 x 16 (transposed store)
    int vrow = tid >> 4, vcol = (tid & 15) * 4;    // 16 x 128 (two float4 per thread)
    int ty = tid >> 5, tx = tid & 31;              // m = ty*8, n = tx*4
    float acc[8][4];
    #pragma unroll
    for (int i = 0; i < 8; i++)
        #pragma unroll
        for (int j = 0; j < 4; j++) acc[i][j] = 0.f;

    int jmax = i0 + 64;                 // rows i0..i0+63 need keys j <= i0+63
    for (int j0 = 0; j0 < jmax; j0 += 16) {
        float4 pv = *(const float4*)(Pb + (size_t)(i0 + prow) * SEQ + j0 + pcol);
        Ps[pcol + 0][prow] = pv.x; Ps[pcol + 1][prow] = pv.y;
        Ps[pcol + 2][prow] = pv.z; Ps[pcol + 3][prow] = pv.w;
        float4 v1 = *(const float4*)(vb + (size_t)(j0 + vrow) * (NKV * HD) + vcol);
        float4 v2 = *(const float4*)(vb + (size_t)(j0 + vrow) * (NKV * HD) + vcol + 64);
        *(float4*)&Vs[vrow][vcol] = v1;
        *(float4*)&Vs[vrow][vcol + 64] = v2;
        __syncthreads();
        #pragma unroll
        for (int kk = 0; kk < 16; kk++) {
            float a[8], bb[4];
            #pragma unroll
            for (int i = 0; i < 8; i++) a[i] = Ps[kk][ty * 8 + i];
            #pragma unroll
            for (int j = 0; j < 4; j++) bb[j] = Vs[kk][tx * 4 + j];
            #pragma unroll
            for (int i = 0; i < 8; i++)
                #pragma unroll
                for (int j = 0; j < 4; j++)
                    acc[i][j] = fmaf(a[i], bb[j], acc[i][j]);
        }
        __syncthreads();
    }
    #pragma unroll
    for (int i = 0; i < 8; i++) {
        size_t base = (((size_t)(b * SEQ + i0 + ty * 8 + i)) * NH + h) * HD + tx * 4;
        float4 vout;
        vout.x = acc[i][0]; vout.y = acc[i][1]; vout.z = acc[i][2]; vout.w = acc[i][3];
        *(float4*)(ctx + base) = vout;
    }
}

// ------------------------- fused SiLU(gate) * up, in place into gate -------------------------
__global__ void silu_mul_kernel(float* __restrict__ g, const float* __restrict__ u, int n) {
    int i = blockIdx.x * blockDim.x + threadIdx.x;
    if (i < n) {
        float x = g[i];
        float s = x / (1.0f + __expf(-x));
        g[i] = s * u[i];
    }
}

// ------------------------- host orchestration -------------------------
extern "C" void kernel_launch(void* const* d_in, const int* in_sizes, int n_in,
                              void* d_out, int out_size) {
    const int*   ids     = (const int*)d_in[0];
    const float* embed   = (const float*)d_in[1];
    const float* Wq      = (const float*)d_in[2];
    const float* Wk      = (const float*)d_in[3];
    const float* Wv      = (const float*)d_in[4];
    const float* Wo      = (const float*)d_in[5];
    const float* qn      = (const float*)d_in[6];
    const float* kn      = (const float*)d_in[7];
    const float* ln1     = (const float*)d_in[8];
    const float* ln2     = (const float*)d_in[9];
    const float* Wg      = (const float*)d_in[10];
    const float* Wu      = (const float*)d_in[11];
    const float* Wd      = (const float*)d_in[12];
    const float* norm_w  = (const float*)d_in[13];
    const float* lm_head = (const float*)d_in[14];
    float* out = (float*)d_out;
    (void)in_sizes; (void)n_in; (void)out_size;

    float *ph, *px, *pq, *pk, *pv, *psc, *pctx, *pg, *pu;
    cudaGetSymbolAddress((void**)&ph,   g_h);
    cudaGetSymbolAddress((void**)&px,   g_x);
    cudaGetSymbolAddress((void**)&pq,   g_q);
    cudaGetSymbolAddress((void**)&pk,   g_k);
    cudaGetSymbolAddress((void**)&pv,   g_v);
    cudaGetSymbolAddress((void**)&psc,  g_sc);
    cudaGetSymbolAddress((void**)&pctx, g_ctx);
    cudaGetSymbolAddress((void**)&pg,   g_gate);
    cudaGetSymbolAddress((void**)&pu,   g_up);

    rope_table_kernel<<<SEQ, 64>>>();
    embed_kernel<<<T, 256>>>(ids, embed, ph);

    for (int l = 0; l < NLAYER; l++) {
        rmsnorm_kernel<<<T, 256>>>(ph, ln1 + (size_t)l * H, px);

        sgemm_nn<<<dim3((NH * HD) / 128, T / 128), 256>>>(px, Wq + (size_t)l * H * NH * HD, pq, T, NH * HD, H, 0);
        sgemm_nn<<<dim3((NKV * HD) / 128, T / 128), 256>>>(px, Wk + (size_t)l * H * NKV * HD, pk, T, NKV * HD, H, 0);
        sgemm_nn<<<dim3((NKV * HD) / 128, T / 128), 256>>>(px, Wv + (size_t)l * H * NKV * HD, pv, T, NKV * HD, H, 0);

        qknorm_rope_kernel<<<dim3(T, NH), HD>>>(pq, qn + (size_t)l * HD, NH);
        qknorm_rope_kernel<<<dim3(T, NKV), HD>>>(pk, kn + (size_t)l * HD, NKV);

        attn_scores_kernel<<<dim3(SEQ / 64, SEQ / 64, BATCH * NH), 256>>>(pq, pk, psc);
        softmax_kernel<<<dim3(SEQ, BATCH * NH), 256>>>(psc);
        attn_ctx_kernel<<<dim3(SEQ / 64, BATCH * NH), 256>>>(psc, pv, pctx);

        sgemm_nn<<<dim3(H / 128, T / 128), 256>>>(pctx, Wo + (size_t)l * NH * HD * H, ph, T, H, NH * HD, 1);

        rmsnorm_kernel<<<T, 256>>>(ph, ln2 + (size_t)l * H, px);
        sgemm_nn<<<dim3(FFI / 128, T / 128), 256>>>(px, Wg + (size_t)l * H * FFI, pg, T, FFI, H, 0);
        sgemm_nn<<<dim3(FFI / 128, T / 128), 256>>>(px, Wu + (size_t)l * H * FFI, pu, T, FFI, H, 0);
        silu_mul_kernel<<<(T * FFI + 255) / 256, 256>>>(pg, pu, T * FFI);
        sgemm_nn<<<dim3(H / 128, T / 128), 256>>>(pg, Wd + (size_t)l * FFI * H, ph, T, H, FFI, 1);
    }

    rmsnorm_kernel<<<T, 256>>>(ph, norm_w, px);
    sgemm_nn<<<dim3(VOC / 128, T / 128), 256>>>(px, lm_head, out, T, VOC, H, 0);
}

// round 6
// speedup vs baseline: 1.4646x; 1.4646x over previous
#include <cuda_runtime.h>
#include <math.h>

#define NLAYER 8
#define H 1024
#define NH 16
#define NKV 8
#define HD 128
#define FFI 3072
#define VOC 32000
#define BATCH 2
#define SEQ 1024
#define T (BATCH*SEQ)

// ------------------------- scratch (device globals; no allocs) -------------------------
__device__ float g_h[T*H];                                   // residual stream  (8 MB)
__device__ float g_x[T*H];                                   // normed activations
__device__ float g_q[T*NH*HD];                               // 16 MB
__device__ float g_k[T*NKV*HD];                               // 8 MB
__device__ float g_v[T*NKV*HD];                               // 8 MB
__device__ float g_sc[(size_t)BATCH*NH*SEQ*SEQ];             // 134 MB scores/probs
__device__ float g_ctx[T*NH*HD];                              // 16 MB
__device__ float g_gate[T*FFI];                               // 24 MB
__device__ float g_up[T*FFI];                                 // 24 MB
__device__ float g_cos[SEQ*64];
__device__ float g_sin[SEQ*64];

// ------------------------- rope tables (double precision once) -------------------------
__global__ void rope_table_kernel() {
    int pos = blockIdx.x;
    int j = threadIdx.x;                       // 0..63
    double inv = pow(1.0e6, -((double)(2 * j)) / 128.0);
    double ang = (double)pos * inv;
    g_cos[pos * 64 + j] = (float)cos(ang);
    g_sin[pos * 64 + j] = (float)sin(ang);
}

// ------------------------- embedding gather -------------------------
__global__ void embed_kernel(const int* __restrict__ ids, const float* __restrict__ emb,
                             float* __restrict__ out) {
    int t = blockIdx.x;
    int id = ids[t];
    const float4* src = (const float4*)(emb + (size_t)id * H);
    float4* dst = (float4*)(out + (size_t)t * H);
    dst[threadIdx.x] = src[threadIdx.x];       // 256 threads * float4 = 1024 floats
}

// ------------------------- rmsnorm over H=1024 -------------------------
__global__ __launch_bounds__(256) void rmsnorm_kernel(const float* __restrict__ in,
                                                      const float* __restrict__ w,
                                                      float* __restrict__ out) {
    int r = blockIdx.x, tid = threadIdx.x;
    const float4* ip = (const float4*)(in + (size_t)r * H);
    float4 v = ip[tid];
    float sq = v.x*v.x + v.y*v.y + v.z*v.z + v.w*v.w;
    __shared__ float red[8];
    __shared__ float s_scale;
    #pragma unroll
    for (int o = 16; o > 0; o >>= 1) sq += __shfl_xor_sync(0xffffffffu, sq, o);
    if ((tid & 31) == 0) red[tid >> 5] = sq;
    __syncthreads();
    if (tid == 0) {
        float t2 = 0.f;
        #pragma unroll
        for (int i = 0; i < 8; i++) t2 += red[i];
        s_scale = rsqrtf(t2 * (1.0f / H) + 1e-6f);
    }
    __syncthreads();
    float sc = s_scale;
    float4 wv = ((const float4*)w)[tid];
    float4 o;
    o.x = v.x * sc * wv.x; o.y = v.y * sc * wv.y;
    o.z = v.z * sc * wv.z; o.w = v.w * sc * wv.w;
    ((float4*)(out + (size_t)r * H))[tid] = o;
}

// ------------------------- per-head rmsnorm + rope (in place) -------------------------
__global__ __launch_bounds__(HD) void qknorm_rope_kernel(float* __restrict__ x,
                                                         const float* __restrict__ w,
                                                         int nheads) {
    int t = blockIdx.x;                 // token 0..T-1
    int hh = blockIdx.y;
    int d = threadIdx.x;                // 0..127
    float* p = x + ((size_t)t * nheads + hh) * HD;
    float val = p[d];
    float sq = val * val;
    #pragma unroll
    for (int o = 16; o > 0; o >>= 1) sq += __shfl_xor_sync(0xffffffffu, sq, o);
    __shared__ float red[4];
    __shared__ float sh[HD];
    if ((d & 31) == 0) red[d >> 5] = sq;
    __syncthreads();
    float tot = red[0] + red[1] + red[2] + red[3];
    float rms = rsqrtf(tot * (1.0f / HD) + 1e-6f);
    float xn = val * rms * w[d];
    sh[d] = xn;
    __syncthreads();
    int pos = t & (SEQ - 1);
    int j = d & 63;
    float c = g_cos[pos * 64 + j];
    float s = g_sin[pos * 64 + j];
    float out = (d < 64) ? (xn * c - sh[d + 64] * s)
                         : (xn * c + sh[d - 64] * s);
    p[d] = out;
}

// ------------------------- tf32x3 tensor-core SGEMM -------------------------
// C (+)= A[MxK] @ B[KxN], row-major, fp32 in/out, near-fp32 accuracy via
// hi*hi + hi*lo + lo*hi (3xTF32). M%128==0, N%128==0, K%32==0.
__device__ __forceinline__ unsigned f2tf(float x) {
    unsigned r;
    asm("cvt.rna.tf32.f32 %0, %1;" : "=r"(r) : "f"(x));
    return r;
}

#define MMA_TF32(c, a, b) \
    asm volatile("mma.sync.aligned.m16n8k8.row.col.f32.tf32.tf32.f32 " \
                 "{%0,%1,%2,%3}, {%4,%5,%6,%7}, {%8,%9}, {%0,%1,%2,%3};\n" \
                 : "+f"(c[0]), "+f"(c[1]), "+f"(c[2]), "+f"(c[3]) \
                 : "r"(a[0]), "r"(a[1]), "r"(a[2]), "r"(a[3]), \
                   "r"(b[0]), "r"(b[1]))

__global__ __launch_bounds__(256, 2) void sgemm_tf32(const float* __restrict__ A,
                                                     const float* __restrict__ B,
                                                     float* __restrict__ C,
                                                     int M, int N, int K, int accum) {
    // padded strides chosen for conflict-free fragment LDS:
    //   A: bank(m*36 + k)   = (4*gid + tg) % 32  -> all 32 lanes distinct
    //   B: bank(k*136 + n)  = (8*tg + gid) % 32  -> all 32 lanes distinct
    __shared__ float As[128][36];    // 18432 B
    __shared__ float Bs[32][136];    // 17408 B

    int tid = threadIdx.x;
    int bm = blockIdx.y * 128, bn = blockIdx.x * 128;
    int w = tid >> 5, lane = tid & 31;
    int gid = lane >> 2, tg = lane & 3;
    int wm = (w >> 2) * 64;          // warp row: 0 / 64
    int wn = (w & 3) * 32;           // warp col: 0/32/64/96

    // global->shared load assignment
    int arow = tid >> 1;             // 0..127
    int acol = (tid & 1) * 16;       // 0 / 16
    int brow = tid >> 3;             // 0..31
    int bcol = (tid & 7) * 16;       // 0..112
    const float* Ag = A + (size_t)(bm + arow) * K + acol;
    const float* Bg = B + (size_t)brow * N + bn + bcol;

    float acc[4][4][4];
    #pragma unroll
    for (int mt = 0; mt < 4; mt++)
        #pragma unroll
        for (int nt = 0; nt < 4; nt++)
            #pragma unroll
            for (int r = 0; r < 4; r++) acc[mt][nt][r] = 0.f;

    for (int k0 = 0; k0 < K; k0 += 32) {
        #pragma unroll
        for (int q = 0; q < 4; q++) {
            float4 v = *(const float4*)(Ag + k0 + q * 4);
            *(float4*)&As[arow][acol + q * 4] = v;
        }
        #pragma unroll
        for (int q = 0; q < 4; q++) {
            float4 v = *(const float4*)(Bg + (size_t)k0 * N + q * 4);
            *(float4*)&Bs[brow][bcol + q * 4] = v;
        }
        __syncthreads();

        #pragma unroll
        for (int ks = 0; ks < 4; ks++) {
            int kb = ks * 8;
            // B fragments (hi/lo) for the 4 n-tiles
            unsigned bh[4][2], bl[4][2];
            #pragma unroll
            for (int nt = 0; nt < 4; nt++) {
                int n = wn + nt * 8 + gid;
                float v0 = Bs[kb + tg][n];
                float v1 = Bs[kb + tg + 4][n];
                bh[nt][0] = f2tf(v0);
                bh[nt][1] = f2tf(v1);
                bl[nt][0] = f2tf(v0 - __uint_as_float(bh[nt][0]));
                bl[nt][1] = f2tf(v1 - __uint_as_float(bh[nt][1]));
            }
            #pragma unroll
            for (int mt = 0; mt < 4; mt++) {
                int m = wm + mt * 16 + gid;
                float a0 = As[m][kb + tg];
                float a1 = As[m + 8][kb + tg];
                float a2 = As[m][kb + tg + 4];
                float a3 = As[m + 8][kb + tg + 4];
                unsigned ah[4], al[4];
                ah[0] = f2tf(a0); ah[1] = f2tf(a1);
                ah[2] = f2tf(a2); ah[3] = f2tf(a3);
                al[0] = f2tf(a0 - __uint_as_float(ah[0]));
                al[1] = f2tf(a1 - __uint_as_float(ah[1]));
                al[2] = f2tf(a2 - __uint_as_float(ah[2]));
                al[3] = f2tf(a3 - __uint_as_float(ah[3]));
                #pragma unroll
                for (int nt = 0; nt < 4; nt++) {
                    MMA_TF32(acc[mt][nt], ah, bh[nt]);
                    MMA_TF32(acc[mt][nt], ah, bl[nt]);
                    MMA_TF32(acc[mt][nt], al, bh[nt]);
                }
            }
        }
        __syncthreads();
    }

    // epilogue: each (mt,nt) tile -> rows (gid, gid+8), cols (tg*2, tg*2+1)
    #pragma unroll
    for (int mt = 0; mt < 4; mt++) {
        #pragma unroll
        for (int nt = 0; nt < 4; nt++) {
            int row0 = bm + wm + mt * 16 + gid;
            int col = bn + wn + nt * 8 + tg * 2;
            float* Cp0 = C + (size_t)row0 * N + col;
            float* Cp1 = C + (size_t)(row0 + 8) * N + col;
            if (accum) {
                float2 o0 = *(float2*)Cp0;
                float2 o1 = *(float2*)Cp1;
                *(float2*)Cp0 = make_float2(o0.x + acc[mt][nt][0], o0.y + acc[mt][nt][1]);
                *(float2*)Cp1 = make_float2(o1.x + acc[mt][nt][2], o1.y + acc[mt][nt][3]);
            } else {
                *(float2*)Cp0 = make_float2(acc[mt][nt][0], acc[mt][nt][1]);
                *(float2*)Cp1 = make_float2(acc[mt][nt][2], acc[mt][nt][3]);
            }
        }
    }
}

// ------------------------- attention scores: S[z,i,j] = scale * q_i . k_j (NT) -------------------------
__global__ __launch_bounds__(256) void attn_scores_kernel(const float* __restrict__ q,
                                                          const float* __restrict__ k,
                                                          float* __restrict__ sc) {
    int z = blockIdx.z;                 // b*NH + h
    int b = z >> 4, h = z & 15;
    int i0 = blockIdx.y * 64, j0 = blockIdx.x * 64;
    if (j0 > i0 + 63) return;           // strictly-upper tile: never read by softmax
    const float* qb = q + ((size_t)b * SEQ * NH + h) * HD;
    const float* kb = k + ((size_t)b * SEQ * NKV + (h >> 1)) * HD;
    __shared__ float Qs[16][64];
    __shared__ float Ks[16][64];
    int tid = threadIdx.x;
    int lrow = tid >> 2;                // 0..63
    int lcol = (tid & 3) * 4;           // 0,4,8,12
    int ty = tid >> 4, tx = tid & 15;
    float acc[4][4];
    #pragma unroll
    for (int i = 0; i < 4; i++)
        #pragma unroll
        for (int j = 0; j < 4; j++) acc[i][j] = 0.f;

    for (int d0 = 0; d0 < HD; d0 += 16) {
        float4 qv = *(const float4*)(qb + (size_t)(i0 + lrow) * (NH * HD) + d0 + lcol);
        float4 kv = *(const float4*)(kb + (size_t)(j0 + lrow) * (NKV * HD) + d0 + lcol);
        Qs[lcol + 0][lrow] = qv.x; Qs[lcol + 1][lrow] = qv.y;
        Qs[lcol + 2][lrow] = qv.z; Qs[lcol + 3][lrow] = qv.w;
        Ks[lcol + 0][lrow] = kv.x; Ks[lcol + 1][lrow] = kv.y;
        Ks[lcol + 2][lrow] = kv.z; Ks[lcol + 3][lrow] = kv.w;
        __syncthreads();
        #pragma unroll
        for (int d = 0; d < 16; d++) {
            float a[4], bb[4];
            #pragma unroll
            for (int i = 0; i < 4; i++) a[i] = Qs[d][ty * 4 + i];
            #pragma unroll
            for (int j = 0; j < 4; j++) bb[j] = Ks[d][tx * 4 + j];
            #pragma unroll
            for (int i = 0; i < 4; i++)
                #pragma unroll
                for (int j = 0; j < 4; j++)
                    acc[i][j] = fmaf(a[i], bb[j], acc[i][j]);
        }
        __syncthreads();
    }
    const float scale = 0.08838834764831845f;   // 1/sqrt(128)
    size_t zoff = (size_t)z * SEQ * SEQ;
    #pragma unroll
    for (int i = 0; i < 4; i++)
        #pragma unroll
        for (int j = 0; j < 4; j++)
            sc[zoff + (size_t)(i0 + ty * 4 + i) * SEQ + j0 + tx * 4 + j] = acc[i][j] * scale;
}

// ------------------------- causal softmax, row-wise (in place) -------------------------
__global__ __launch_bounds__(256) void softmax_kernel(float* __restrict__ sc) {
    int i = blockIdx.x;
    int z = blockIdx.y;
    float* row = sc + (size_t)z * SEQ * SEQ + (size_t)i * SEQ;
    int len = i + 1;
    int tid = threadIdx.x;
    __shared__ float red[8];
    float m = -1e30f;
    for (int j = tid; j < len; j += 256) m = fmaxf(m, row[j]);
    #pragma unroll
    for (int o = 16; o > 0; o >>= 1) m = fmaxf(m, __shfl_xor_sync(0xffffffffu, m, o));
    if ((tid & 31) == 0) red[tid >> 5] = m;
    __syncthreads();
    if (tid == 0) {
        float t = red[0];
        #pragma unroll
        for (int w = 1; w < 8; w++) t = fmaxf(t, red[w]);
        red[0] = t;
    }
    __syncthreads();
    float bm = red[0];
    __syncthreads();
    float s = 0.f;
    for (int j = tid; j < len; j += 256) s += __expf(row[j] - bm);
    #pragma unroll
    for (int o = 16; o > 0; o >>= 1) s += __shfl_xor_sync(0xffffffffu, s, o);
    if ((tid & 31) == 0) red[tid >> 5] = s;
    __syncthreads();
    if (tid == 0) {
        float t = 0.f;
        #pragma unroll
        for (int w = 0; w < 8; w++) t += red[w];
        red[0] = 1.0f / t;
    }
    __syncthreads();
    float inv = red[0];
    for (int j = tid; j < SEQ; j += 256)
        row[j] = (j < len) ? __expf(row[j] - bm) * inv : 0.f;
}

// ------------------------- ctx: C[i,:] = sum_j P[i,j] * V[j,:]  (NN, K-loop stops at diagonal) -------------------------
__global__ __launch_bounds__(256) void attn_ctx_kernel(const float* __restrict__ P,
                                                       const float* __restrict__ v,
                                                       float* __restrict__ ctx) {
    int z = blockIdx.y;                 // b*NH + h
    int b = z >> 4, h = z & 15;
    int i0 = blockIdx.x * 64;
    const float* Pb = P + (size_t)z * SEQ * SEQ;
    const float* vb = v + ((size_t)b * SEQ * NKV + (h >> 1)) * HD;
    __shared__ float Ps[16][64];
    __shared__ float Vs[16][128];
    int tid = threadIdx.x;
    int prow = tid >> 2, pcol = (tid & 3) * 4;     // 64 x 16 (transposed store)
    int vrow = tid >> 4, vcol = (tid & 15) * 4;    // 16 x 128 (two float4 per thread)
    int ty = tid >> 5, tx = tid & 31;              // m = ty*8, n = tx*4
    float acc[8][4];
    #pragma unroll
    for (int i = 0; i < 8; i++)
        #pragma unroll
        for (int j = 0; j < 4; j++) acc[i][j] = 0.f;

    int jmax = i0 + 64;                 // rows i0..i0+63 need keys j <= i0+63
    for (int j0 = 0; j0 < jmax; j0 += 16) {
        float4 pv = *(const float4*)(Pb + (size_t)(i0 + prow) * SEQ + j0 + pcol);
        Ps[pcol + 0][prow] = pv.x; Ps[pcol + 1][prow] = pv.y;
        Ps[pcol + 2][prow] = pv.z; Ps[pcol + 3][prow] = pv.w;
        float4 v1 = *(const float4*)(vb + (size_t)(j0 + vrow) * (NKV * HD) + vcol);
        float4 v2 = *(const float4*)(vb + (size_t)(j0 + vrow) * (NKV * HD) + vcol + 64);
        *(float4*)&Vs[vrow][vcol] = v1;
        *(float4*)&Vs[vrow][vcol + 64] = v2;
        __syncthreads();
        #pragma unroll
        for (int kk = 0; kk < 16; kk++) {
            float a[8], bb[4];
            #pragma unroll
            for (int i = 0; i < 8; i++) a[i] = Ps[kk][ty * 8 + i];
            #pragma unroll
            for (int j = 0; j < 4; j++) bb[j] = Vs[kk][tx * 4 + j];
            #pragma unroll
            for (int i = 0; i < 8; i++)
                #pragma unroll
                for (int j = 0; j < 4; j++)
                    acc[i][j] = fmaf(a[i], bb[j], acc[i][j]);
        }
        __syncthreads();
    }
    #pragma unroll
    for (int i = 0; i < 8; i++) {
        size_t base = (((size_t)(b * SEQ + i0 + ty * 8 + i)) * NH + h) * HD + tx * 4;
        float4 vout;
        vout.x = acc[i][0]; vout.y = acc[i][1]; vout.z = acc[i][2]; vout.w = acc[i][3];
        *(float4*)(ctx + base) = vout;
    }
}

// ------------------------- fused SiLU(gate) * up, in place into gate -------------------------
__global__ void silu_mul_kernel(float* __restrict__ g, const float* __restrict__ u, int n) {
    int i = blockIdx.x * blockDim.x + threadIdx.x;
    if (i < n) {
        float x = g[i];
        float s = x / (1.0f + __expf(-x));
        g[i] = s * u[i];
    }
}

// ------------------------- host orchestration -------------------------
extern "C" void kernel_launch(void* const* d_in, const int* in_sizes, int n_in,
                              void* d_out, int out_size) {
    const int*   ids     = (const int*)d_in[0];
    const float* embed   = (const float*)d_in[1];
    const float* Wq      = (const float*)d_in[2];
    const float* Wk      = (const float*)d_in[3];
    const float* Wv      = (const float*)d_in[4];
    const float* Wo      = (const float*)d_in[5];
    const float* qn      = (const float*)d_in[6];
    const float* kn      = (const float*)d_in[7];
    const float* ln1     = (const float*)d_in[8];
    const float* ln2     = (const float*)d_in[9];
    const float* Wg      = (const float*)d_in[10];
    const float* Wu      = (const float*)d_in[11];
    const float* Wd      = (const float*)d_in[12];
    const float* norm_w  = (const float*)d_in[13];
    const float* lm_head = (const float*)d_in[14];
    float* out = (float*)d_out;
    (void)in_sizes; (void)n_in; (void)out_size;

    float *ph, *px, *pq, *pk, *pv, *psc, *pctx, *pg, *pu;
    cudaGetSymbolAddress((void**)&ph,   g_h);
    cudaGetSymbolAddress((void**)&px,   g_x);
    cudaGetSymbolAddress((void**)&pq,   g_q);
    cudaGetSymbolAddress((void**)&pk,   g_k);
    cudaGetSymbolAddress((void**)&pv,   g_v);
    cudaGetSymbolAddress((void**)&psc,  g_sc);
    cudaGetSymbolAddress((void**)&pctx, g_ctx);
    cudaGetSymbolAddress((void**)&pg,   g_gate);
    cudaGetSymbolAddress((void**)&pu,   g_up);

    rope_table_kernel<<<SEQ, 64>>>();
    embed_kernel<<<T, 256>>>(ids, embed, ph);

    for (int l = 0; l < NLAYER; l++) {
        rmsnorm_kernel<<<T, 256>>>(ph, ln1 + (size_t)l * H, px);

        sgemm_tf32<<<dim3((NH * HD) / 128, T / 128), 256>>>(px, Wq + (size_t)l * H * NH * HD, pq, T, NH * HD, H, 0);
        sgemm_tf32<<<dim3((NKV * HD) / 128, T / 128), 256>>>(px, Wk + (size_t)l * H * NKV * HD, pk, T, NKV * HD, H, 0);
        sgemm_tf32<<<dim3((NKV * HD) / 128, T / 128), 256>>>(px, Wv + (size_t)l * H * NKV * HD, pv, T, NKV * HD, H, 0);

        qknorm_rope_kernel<<<dim3(T, NH), HD>>>(pq, qn + (size_t)l * HD, NH);
        qknorm_rope_kernel<<<dim3(T, NKV), HD>>>(pk, kn + (size_t)l * HD, NKV);

        attn_scores_kernel<<<dim3(SEQ / 64, SEQ / 64, BATCH * NH), 256>>>(pq, pk, psc);
        softmax_kernel<<<dim3(SEQ, BATCH * NH), 256>>>(psc);
        attn_ctx_kernel<<<dim3(SEQ / 64, BATCH * NH), 256>>>(psc, pv, pctx);

        sgemm_tf32<<<dim3(H / 128, T / 128), 256>>>(pctx, Wo + (size_t)l * NH * HD * H, ph, T, H, NH * HD, 1);

        rmsnorm_kernel<<<T, 256>>>(ph, ln2 + (size_t)l * H, px);
        sgemm_tf32<<<dim3(FFI / 128, T / 128), 256>>>(px, Wg + (size_t)l * H * FFI, pg, T, FFI, H, 0);
        sgemm_tf32<<<dim3(FFI / 128, T / 128), 256>>>(px, Wu + (size_t)l * H * FFI, pu, T, FFI, H, 0);
        silu_mul_kernel<<<(T * FFI + 255) / 256, 256>>>(pg, pu, T * FFI);
        sgemm_tf32<<<dim3(H / 128, T / 128), 256>>>(pg, Wd + (size_t)l * FFI * H, ph, T, H, FFI, 1);
    }

    rmsnorm_kernel<<<T, 256>>>(ph, norm_w, px);
    sgemm_tf32<<<dim3(VOC / 128, T / 128), 256>>>(px, lm_head, out, T, VOC, H, 0);
}

// round 7
// speedup vs baseline: 1.8726x; 1.2786x over previous
#include <cuda_runtime.h>
#include <cuda_bf16.h>
#include <math.h>

#define NLAYER 8
#define H 1024
#define NH 16
#define NKV 8
#define HD 128
#define FFI 3072
#define VOC 32000
#define BATCH 2
#define SEQ 1024
#define T (BATCH*SEQ)

// ------------------------- scratch (device globals; no allocs) -------------------------
__device__ float g_h[T*H];
__device__ float g_x[T*H];
__device__ float g_q[T*NH*HD];
__device__ float g_k[T*NKV*HD];
__device__ float g_v[T*NKV*HD];
__device__ float g_sc[(size_t)BATCH*NH*SEQ*SEQ];
__device__ float g_ctx[T*NH*HD];
__device__ float g_gate[T*FFI];
__device__ float g_up[T*FFI];
__device__ float g_cos[SEQ*64];
__device__ float g_sin[SEQ*64];

// ------------------------- rope tables (double precision once) -------------------------
__global__ void rope_table_kernel() {
    int pos = blockIdx.x;
    int j = threadIdx.x;
    double inv = pow(1.0e6, -((double)(2 * j)) / 128.0);
    double ang = (double)pos * inv;
    g_cos[pos * 64 + j] = (float)cos(ang);
    g_sin[pos * 64 + j] = (float)sin(ang);
}

// ------------------------- embedding gather -------------------------
__global__ void embed_kernel(const int* __restrict__ ids, const float* __restrict__ emb,
                             float* __restrict__ out) {
    int t = blockIdx.x;
    int id = ids[t];
    const float4* src = (const float4*)(emb + (size_t)id * H);
    float4* dst = (float4*)(out + (size_t)t * H);
    dst[threadIdx.x] = src[threadIdx.x];
}

// ------------------------- rmsnorm over H=1024 -------------------------
__global__ __launch_bounds__(256) void rmsnorm_kernel(const float* __restrict__ in,
                                                      const float* __restrict__ w,
                                                      float* __restrict__ out) {
    int r = blockIdx.x, tid = threadIdx.x;
    const float4* ip = (const float4*)(in + (size_t)r * H);
    float4 v = ip[tid];
    float sq = v.x*v.x + v.y*v.y + v.z*v.z + v.w*v.w;
    __shared__ float red[8];
    __shared__ float s_scale;
    #pragma unroll
    for (int o = 16; o > 0; o >>= 1) sq += __shfl_xor_sync(0xffffffffu, sq, o);
    if ((tid & 31) == 0) red[tid >> 5] = sq;
    __syncthreads();
    if (tid == 0) {
        float t2 = 0.f;
        #pragma unroll
        for (int i = 0; i < 8; i++) t2 += red[i];
        s_scale = rsqrtf(t2 * (1.0f / H) + 1e-6f);
    }
    __syncthreads();
    float sc = s_scale;
    float4 wv = ((const float4*)w)[tid];
    float4 o;
    o.x = v.x * sc * wv.x; o.y = v.y * sc * wv.y;
    o.z = v.z * sc * wv.z; o.w = v.w * sc * wv.w;
    ((float4*)(out + (size_t)r * H))[tid] = o;
}

// ------------------------- per-head rmsnorm + rope (in place) -------------------------
__global__ __launch_bounds__(HD) void qknorm_rope_kernel(float* __restrict__ x,
                                                         const float* __restrict__ w,
                                                         int nheads) {
    int t = blockIdx.x;
    int hh = blockIdx.y;
    int d = threadIdx.x;
    float* p = x + ((size_t)t * nheads + hh) * HD;
    float val = p[d];
    float sq = val * val;
    #pragma unroll
    for (int o = 16; o > 0; o >>= 1) sq += __shfl_xor_sync(0xffffffffu, sq, o);
    __shared__ float red[4];
    __shared__ float sh[HD];
    if ((d & 31) == 0) red[d >> 5] = sq;
    __syncthreads();
    float tot = red[0] + red[1] + red[2] + red[3];
    float rms = rsqrtf(tot * (1.0f / HD) + 1e-6f);
    float xn = val * rms * w[d];
    sh[d] = xn;
    __syncthreads();
    int pos = t & (SEQ - 1);
    int j = d & 63;
    float c = g_cos[pos * 64 + j];
    float s = g_sin[pos * 64 + j];
    float out = (d < 64) ? (xn * c - sh[d + 64] * s)
                         : (xn * c + sh[d - 64] * s);
    p[d] = out;
}

// ------------------------- bf16x3 split helpers -------------------------
// x = hi + lo with hi,lo bf16; pack pairs (k even, k odd) into b16x2 regs.
__device__ __forceinline__ unsigned pack_hi(float x, float y, float& rx, float& ry) {
    __nv_bfloat16 bx = __float2bfloat16_rn(x);
    __nv_bfloat16 by = __float2bfloat16_rn(y);
    rx = x - __bfloat162float(bx);
    ry = y - __bfloat162float(by);
    return (unsigned)__bfloat16_as_ushort(bx) | ((unsigned)__bfloat16_as_ushort(by) << 16);
}
__device__ __forceinline__ unsigned pack_lo(float rx, float ry) {
    return (unsigned)__bfloat16_as_ushort(__float2bfloat16_rn(rx)) |
           ((unsigned)__bfloat16_as_ushort(__float2bfloat16_rn(ry)) << 16);
}

#define MMA_BF16(c, a, b) \
    asm volatile("mma.sync.aligned.m16n8k16.row.col.f32.bf16.bf16.f32 " \
                 "{%0,%1,%2,%3}, {%4,%5,%6,%7}, {%8,%9}, {%0,%1,%2,%3};\n" \
                 : "+f"(c[0]), "+f"(c[1]), "+f"(c[2]), "+f"(c[3]) \
                 : "r"(a[0]), "r"(a[1]), "r"(a[2]), "r"(a[3]), \
                   "r"(b[0]), "r"(b[1]))

// Shared-tile layout: [row 0..127][kpair 0..15], stride 20 -> fragment LDS
// bank = (20*gid + tg) mod 32, all 32 lanes distinct (conflict-free).
#define KP_STRIDE 20

// inner MMA body over one 32-K chunk held in Ah/Al/Bh/Bl  (rows x kpairs)
#define MMA_CHUNK_BODY(Ah, Al, Bh, Bl, acc, wm, wn, gid, tg)                    \
    _Pragma("unroll")                                                           \
    for (int s = 0; s < 2; s++) {                                               \
        int kb = s * 8;                                                         \
        unsigned bh[4][2], bl[4][2];                                            \
        _Pragma("unroll")                                                       \
        for (int nt = 0; nt < 4; nt++) {                                        \
            int n = wn + nt * 8 + gid;                                          \
            bh[nt][0] = Bh[n][kb + tg];  bh[nt][1] = Bh[n][kb + tg + 4];        \
            bl[nt][0] = Bl[n][kb + tg];  bl[nt][1] = Bl[n][kb + tg + 4];        \
        }                                                                       \
        _Pragma("unroll")                                                       \
        for (int mt = 0; mt < 4; mt++) {                                        \
            int m0 = wm + mt * 16 + gid;                                        \
            unsigned ah[4], al[4];                                              \
            ah[0] = Ah[m0][kb + tg];      ah[1] = Ah[m0 + 8][kb + tg];          \
            ah[2] = Ah[m0][kb + tg + 4];  ah[3] = Ah[m0 + 8][kb + tg + 4];      \
            al[0] = Al[m0][kb + tg];      al[1] = Al[m0 + 8][kb + tg];          \
            al[2] = Al[m0][kb + tg + 4];  al[3] = Al[m0 + 8][kb + tg + 4];      \
            _Pragma("unroll")                                                   \
            for (int nt = 0; nt < 4; nt++) {                                    \
                MMA_BF16(acc[mt][nt], ah, bh[nt]);                              \
                MMA_BF16(acc[mt][nt], ah, bl[nt]);                              \
                MMA_BF16(acc[mt][nt], al, bh[nt]);                              \
            }                                                                   \
        }                                                                       \
    }

// ------------------------- dense GEMM: C (+)= A[MxK] @ B[KxN], bf16x3 -------------------------
__global__ __launch_bounds__(256, 2) void gemm_bf16x3(const float* __restrict__ A,
                                                      const float* __restrict__ B,
                                                      float* __restrict__ C,
                                                      int M, int N, int K, int accum) {
    __shared__ unsigned Ah[128][KP_STRIDE], Al[128][KP_STRIDE];
    __shared__ unsigned Bh[128][KP_STRIDE], Bl[128][KP_STRIDE];
    int tid = threadIdx.x;
    int bm = blockIdx.y * 128, bn = blockIdx.x * 128;
    int w = tid >> 5, lane = tid & 31, gid = lane >> 2, tg = lane & 3;
    int wm = (w >> 2) * 64, wn = (w & 3) * 32;

    int arow = tid >> 1, ak0 = (tid & 1) * 8;        // A: row-major, k-contiguous
    int bnn = tid & 127,  bk0 = (tid >> 7) * 8;      // B: k-major rows, transpose on fill
    const float* Ag = A + (size_t)(bm + arow) * K + ak0 * 2;
    const float* Bg = B + bn + bnn;

    float acc[4][4][4];
    #pragma unroll
    for (int mt = 0; mt < 4; mt++)
        #pragma unroll
        for (int nt = 0; nt < 4; nt++)
            #pragma unroll
            for (int r = 0; r < 4; r++) acc[mt][nt][r] = 0.f;

    for (int k0 = 0; k0 < K; k0 += 32) {
        #pragma unroll
        for (int q = 0; q < 4; q++) {
            float4 v = *(const float4*)(Ag + k0 + q * 4);
            float rx, ry;
            Ah[arow][ak0 + q*2    ] = pack_hi(v.x, v.y, rx, ry);
            Al[arow][ak0 + q*2    ] = pack_lo(rx, ry);
            Ah[arow][ak0 + q*2 + 1] = pack_hi(v.z, v.w, rx, ry);
            Al[arow][ak0 + q*2 + 1] = pack_lo(rx, ry);
        }
        #pragma unroll
        for (int i = 0; i < 8; i++) {
            float x = Bg[(size_t)(k0 + bk0*2 + 2*i    ) * N];
            float y = Bg[(size_t)(k0 + bk0*2 + 2*i + 1) * N];
            float rx, ry;
            Bh[bnn][bk0 + i] = pack_hi(x, y, rx, ry);
            Bl[bnn][bk0 + i] = pack_lo(rx, ry);
        }
        __syncthreads();
        MMA_CHUNK_BODY(Ah, Al, Bh, Bl, acc, wm, wn, gid, tg)
        __syncthreads();
    }

    #pragma unroll
    for (int mt = 0; mt < 4; mt++) {
        #pragma unroll
        for (int nt = 0; nt < 4; nt++) {
            int row0 = bm + wm + mt * 16 + gid;
            int col = bn + wn + nt * 8 + tg * 2;
            float* Cp0 = C + (size_t)row0 * N + col;
            float* Cp1 = C + (size_t)(row0 + 8) * N + col;
            if (accum) {
                float2 o0 = *(float2*)Cp0;
                float2 o1 = *(float2*)Cp1;
                *(float2*)Cp0 = make_float2(o0.x + acc[mt][nt][0], o0.y + acc[mt][nt][1]);
                *(float2*)Cp1 = make_float2(o1.x + acc[mt][nt][2], o1.y + acc[mt][nt][3]);
            } else {
                *(float2*)Cp0 = make_float2(acc[mt][nt][0], acc[mt][nt][1]);
                *(float2*)Cp1 = make_float2(acc[mt][nt][2], acc[mt][nt][3]);
            }
        }
    }
}

// ------------------------- attention scores (NT, bf16x3, causal tile-skip) -------------------------
// S[z, i, j] = scale * q_i . k_j ; both q and k rows are d-contiguous -> both fill A-style.
__global__ __launch_bounds__(256, 2) void attn_scores_mma(const float* __restrict__ q,
                                                          const float* __restrict__ k,
                                                          float* __restrict__ sc) {
    int z = blockIdx.z, b = z >> 4, h = z & 15;
    int i0 = blockIdx.y * 128, j0 = blockIdx.x * 128;
    if (j0 > i0) return;                      // strictly-upper tiles never read
    __shared__ unsigned Ah[128][KP_STRIDE], Al[128][KP_STRIDE];
    __shared__ unsigned Bh[128][KP_STRIDE], Bl[128][KP_STRIDE];
    int tid = threadIdx.x;
    int w = tid >> 5, lane = tid & 31, gid = lane >> 2, tg = lane & 3;
    int wm = (w >> 2) * 64, wn = (w & 3) * 32;
    int arow = tid >> 1, ak0 = (tid & 1) * 8;

    const float* Ag = q + ((size_t)b * SEQ * NH + h) * HD + (size_t)(i0 + arow) * (NH * HD) + ak0 * 2;
    const float* Bg = k + ((size_t)b * SEQ * NKV + (h >> 1)) * HD + (size_t)(j0 + arow) * (NKV * HD) + ak0 * 2;

    float acc[4][4][4];
    #pragma unroll
    for (int mt = 0; mt < 4; mt++)
        #pragma unroll
        for (int nt = 0; nt < 4; nt++)
            #pragma unroll
            for (int r = 0; r < 4; r++) acc[mt][nt][r] = 0.f;

    for (int d0 = 0; d0 < HD; d0 += 32) {
        #pragma unroll
        for (int qq = 0; qq < 4; qq++) {
            float4 v = *(const float4*)(Ag + d0 + qq * 4);
            float rx, ry;
            Ah[arow][ak0 + qq*2    ] = pack_hi(v.x, v.y, rx, ry);
            Al[arow][ak0 + qq*2    ] = pack_lo(rx, ry);
            Ah[arow][ak0 + qq*2 + 1] = pack_hi(v.z, v.w, rx, ry);
            Al[arow][ak0 + qq*2 + 1] = pack_lo(rx, ry);
            float4 u = *(const float4*)(Bg + d0 + qq * 4);
            Bh[arow][ak0 + qq*2    ] = pack_hi(u.x, u.y, rx, ry);
            Bl[arow][ak0 + qq*2    ] = pack_lo(rx, ry);
            Bh[arow][ak0 + qq*2 + 1] = pack_hi(u.z, u.w, rx, ry);
            Bl[arow][ak0 + qq*2 + 1] = pack_lo(rx, ry);
        }
        __syncthreads();
        MMA_CHUNK_BODY(Ah, Al, Bh, Bl, acc, wm, wn, gid, tg)
        __syncthreads();
    }

    const float scale = 0.08838834764831845f;  // 1/sqrt(128)
    size_t zoff = (size_t)z * SEQ * SEQ;
    #pragma unroll
    for (int mt = 0; mt < 4; mt++) {
        #pragma unroll
        for (int nt = 0; nt < 4; nt++) {
            int row0 = i0 + wm + mt * 16 + gid;
            int col = j0 + wn + nt * 8 + tg * 2;
            *(float2*)(sc + zoff + (size_t)row0 * SEQ + col) =
                make_float2(acc[mt][nt][0] * scale, acc[mt][nt][1] * scale);
            *(float2*)(sc + zoff + (size_t)(row0 + 8) * SEQ + col) =
                make_float2(acc[mt][nt][2] * scale, acc[mt][nt][3] * scale);
        }
    }
}

// ------------------------- causal softmax, row-wise (in place) -------------------------
__global__ __launch_bounds__(256) void softmax_kernel(float* __restrict__ sc) {
    int i = blockIdx.x;
    int z = blockIdx.y;
    float* row = sc + (size_t)z * SEQ * SEQ + (size_t)i * SEQ;
    int len = i + 1;
    int tid = threadIdx.x;
    __shared__ float red[8];
    float m = -1e30f;
    for (int j = tid; j < len; j += 256) m = fmaxf(m, row[j]);
    #pragma unroll
    for (int o = 16; o > 0; o >>= 1) m = fmaxf(m, __shfl_xor_sync(0xffffffffu, m, o));
    if ((tid & 31) == 0) red[tid >> 5] = m;
    __syncthreads();
    if (tid == 0) {
        float t = red[0];
        #pragma unroll
        for (int w = 1; w < 8; w++) t = fmaxf(t, red[w]);
        red[0] = t;
    }
    __syncthreads();
    float bm = red[0];
    __syncthreads();
    float s = 0.f;
    for (int j = tid; j < len; j += 256) s += __expf(row[j] - bm);
    #pragma unroll
    for (int o = 16; o > 0; o >>= 1) s += __shfl_xor_sync(0xffffffffu, s, o);
    if ((tid & 31) == 0) red[tid >> 5] = s;
    __syncthreads();
    if (tid == 0) {
        float t = 0.f;
        #pragma unroll
        for (int w = 0; w < 8; w++) t += red[w];
        red[0] = 1.0f / t;
    }
    __syncthreads();
    float inv = red[0];
    for (int j = tid; j < SEQ; j += 256)
        row[j] = (j < len) ? __expf(row[j] - bm) * inv : 0.f;
}

// ------------------------- ctx = P @ V (NN, bf16x3, K-loop stops past diagonal) -------------------------
__global__ __launch_bounds__(256, 2) void attn_ctx_mma(const float* __restrict__ P,
                                                       const float* __restrict__ v,
                                                       float* __restrict__ ctx) {
    int z = blockIdx.y, b = z >> 4, h = z & 15;
    int i0 = blockIdx.x * 128;
    __shared__ unsigned Ah[128][KP_STRIDE], Al[128][KP_STRIDE];
    __shared__ unsigned Bh[128][KP_STRIDE], Bl[128][KP_STRIDE];
    int tid = threadIdx.x;
    int w = tid >> 5, lane = tid & 31, gid = lane >> 2, tg = lane & 3;
    int wm = (w >> 2) * 64, wn = (w & 3) * 32;
    int arow = tid >> 1, ak0 = (tid & 1) * 8;
    int bnn = tid & 127, bk0 = (tid >> 7) * 8;

    const float* Pb = P + (size_t)z * SEQ * SEQ + (size_t)(i0 + arow) * SEQ + ak0 * 2;
    const float* vb = v + ((size_t)b * SEQ * NKV + (h >> 1)) * HD + bnn;

    float acc[4][4][4];
    #pragma unroll
    for (int mt = 0; mt < 4; mt++)
        #pragma unroll
        for (int nt = 0; nt < 4; nt++)
            #pragma unroll
            for (int r = 0; r < 4; r++) acc[mt][nt][r] = 0.f;

    int jmax = i0 + 128;   // P[i][j]==0 for j>i, so full chunks are safe
    for (int k0 = 0; k0 < jmax; k0 += 32) {
        #pragma unroll
        for (int q = 0; q < 4; q++) {
            float4 pv = *(const float4*)(Pb + k0 + q * 4);
            float rx, ry;
            Ah[arow][ak0 + q*2    ] = pack_hi(pv.x, pv.y, rx, ry);
            Al[arow][ak0 + q*2    ] = pack_lo(rx, ry);
            Ah[arow][ak0 + q*2 + 1] = pack_hi(pv.z, pv.w, rx, ry);
            Al[arow][ak0 + q*2 + 1] = pack_lo(rx, ry);
        }
        #pragma unroll
        for (int i = 0; i < 8; i++) {
            float x = vb[(size_t)(k0 + bk0*2 + 2*i    ) * (NKV * HD)];
            float y = vb[(size_t)(k0 + bk0*2 + 2*i + 1) * (NKV * HD)];
            float rx, ry;
            Bh[bnn][bk0 + i] = pack_hi(x, y, rx, ry);
            Bl[bnn][bk0 + i] = pack_lo(rx, ry);
        }
        __syncthreads();
        MMA_CHUNK_BODY(Ah, Al, Bh, Bl, acc, wm, wn, gid, tg)
        __syncthreads();
    }

    #pragma unroll
    for (int mt = 0; mt < 4; mt++) {
        #pragma unroll
        for (int nt = 0; nt < 4; nt++) {
            int row0 = i0 + wm + mt * 16 + gid;
            int col = wn + nt * 8 + tg * 2;
            size_t base0 = (((size_t)(b * SEQ + row0)) * NH + h) * HD + col;
            size_t base1 = (((size_t)(b * SEQ + row0 + 8)) * NH + h) * HD + col;
            *(float2*)(ctx + base0) = make_float2(acc[mt][nt][0], acc[mt][nt][1]);
            *(float2*)(ctx + base1) = make_float2(acc[mt][nt][2], acc[mt][nt][3]);
        }
    }
}

// ------------------------- fused SiLU(gate) * up, in place into gate -------------------------
__global__ void silu_mul_kernel(float* __restrict__ g, const float* __restrict__ u, int n) {
    int i = blockIdx.x * blockDim.x + threadIdx.x;
    if (i < n) {
        float x = g[i];
        float s = x / (1.0f + __expf(-x));
        g[i] = s * u[i];
    }
}

// ------------------------- host orchestration -------------------------
extern "C" void kernel_launch(void* const* d_in, const int* in_sizes, int n_in,
                              void* d_out, int out_size) {
    const int*   ids     = (const int*)d_in[0];
    const float* embed   = (const float*)d_in[1];
    const float* Wq      = (const float*)d_in[2];
    const float* Wk      = (const float*)d_in[3];
    const float* Wv      = (const float*)d_in[4];
    const float* Wo      = (const float*)d_in[5];
    const float* qn      = (const float*)d_in[6];
    const float* kn      = (const float*)d_in[7];
    const float* ln1     = (const float*)d_in[8];
    const float* ln2     = (const float*)d_in[9];
    const float* Wg      = (const float*)d_in[10];
    const float* Wu      = (const float*)d_in[11];
    const float* Wd      = (const float*)d_in[12];
    const float* norm_w  = (const float*)d_in[13];
    const float* lm_head = (const float*)d_in[14];
    float* out = (float*)d_out;
    (void)in_sizes; (void)n_in; (void)out_size;

    float *ph, *px, *pq, *pk, *pv, *psc, *pctx, *pg, *pu;
    cudaGetSymbolAddress((void**)&ph,   g_h);
    cudaGetSymbolAddress((void**)&px,   g_x);
    cudaGetSymbolAddress((void**)&pq,   g_q);
    cudaGetSymbolAddress((void**)&pk,   g_k);
    cudaGetSymbolAddress((void**)&pv,   g_v);
    cudaGetSymbolAddress((void**)&psc,  g_sc);
    cudaGetSymbolAddress((void**)&pctx, g_ctx);
    cudaGetSymbolAddress((void**)&pg,   g_gate);
    cudaGetSymbolAddress((void**)&pu,   g_up);

    rope_table_kernel<<<SEQ, 64>>>();
    embed_kernel<<<T, 256>>>(ids, embed, ph);

    for (int l = 0; l < NLAYER; l++) {
        rmsnorm_kernel<<<T, 256>>>(ph, ln1 + (size_t)l * H, px);

        gemm_bf16x3<<<dim3((NH * HD) / 128, T / 128), 256>>>(px, Wq + (size_t)l * H * NH * HD, pq, T, NH * HD, H, 0);
        gemm_bf16x3<<<dim3((NKV * HD) / 128, T / 128), 256>>>(px, Wk + (size_t)l * H * NKV * HD, pk, T, NKV * HD, H, 0);
        gemm_bf16x3<<<dim3((NKV * HD) / 128, T / 128), 256>>>(px, Wv + (size_t)l * H * NKV * HD, pv, T, NKV * HD, H, 0);

        qknorm_rope_kernel<<<dim3(T, NH), HD>>>(pq, qn + (size_t)l * HD, NH);
        qknorm_rope_kernel<<<dim3(T, NKV), HD>>>(pk, kn + (size_t)l * HD, NKV);

        attn_scores_mma<<<dim3(SEQ / 128, SEQ / 128, BATCH * NH), 256>>>(pq, pk, psc);
        softmax_kernel<<<dim3(SEQ, BATCH * NH), 256>>>(psc);
        attn_ctx_mma<<<dim3(SEQ / 128, BATCH * NH), 256>>>(psc, pv, pctx);

        gemm_bf16x3<<<dim3(H / 128, T / 128), 256>>>(pctx, Wo + (size_t)l * NH * HD * H, ph, T, H, NH * HD, 1);

        rmsnorm_kernel<<<T, 256>>>(ph, ln2 + (size_t)l * H, px);
        gemm_bf16x3<<<dim3(FFI / 128, T / 128), 256>>>(px, Wg + (size_t)l * H * FFI, pg, T, FFI, H, 0);
        gemm_bf16x3<<<dim3(FFI / 128, T / 128), 256>>>(px, Wu + (size_t)l * H * FFI, pu, T, FFI, H, 0);
        silu_mul_kernel<<<(T * FFI + 255) / 256, 256>>>(pg, pu, T * FFI);
        gemm_bf16x3<<<dim3(H / 128, T / 128), 256>>>(pg, Wd + (size_t)l * FFI * H, ph, T, H, FFI, 1);
    }

    rmsnorm_kernel<<<T, 256>>>(ph, norm_w, px);
    gemm_bf16x3<<<dim3(VOC / 128, T / 128), 256>>>(px, lm_head, out, T, VOC, H, 0);
}

// round 12
// speedup vs baseline: 2.7180x; 1.4515x over previous
#include <cuda_runtime.h>
#include <cuda_bf16.h>
#include <math.h>

#define NLAYER 8
#define H 1024
#define NH 16
#define NKV 8
#define HD 128
#define FFI 3072
#define VOC 32000
#define BATCH 2
#define SEQ 1024
#define T (BATCH*SEQ)

// ------------------------- fp32 scratch -------------------------
__device__ float g_h[T*H];
__device__ float g_q[T*NH*HD];
__device__ float g_k[T*NKV*HD];
__device__ float g_v[T*NKV*HD];
__device__ float g_sc[(size_t)BATCH*NH*SEQ*SEQ];
__device__ float g_gate[T*FFI];
__device__ float g_up[T*FFI];
__device__ float g_cos[SEQ*64];
__device__ float g_sin[SEQ*64];

// ------------------------- packed bf16 hi/lo activations (uint = 2 bf16) ----
__device__ unsigned g_xh[T*H/2],   g_xl[T*H/2];
__device__ unsigned g_ctxh[T*NH*HD/2], g_ctxl[T*NH*HD/2];
__device__ unsigned g_gh[T*FFI/2], g_gl[T*FFI/2];

// ------------------------- pre-split transposed weights [N][K] bf16 ----------
__device__ __nv_bfloat16 g_wqh[(size_t)NLAYER*2048*1024], g_wql[(size_t)NLAYER*2048*1024];
__device__ __nv_bfloat16 g_wkh[(size_t)NLAYER*1024*1024], g_wkl[(size_t)NLAYER*1024*1024];
__device__ __nv_bfloat16 g_wvh[(size_t)NLAYER*1024*1024], g_wvl[(size_t)NLAYER*1024*1024];
__device__ __nv_bfloat16 g_woh[(size_t)NLAYER*1024*2048], g_wol[(size_t)NLAYER*1024*2048];
__device__ __nv_bfloat16 g_wgh[(size_t)NLAYER*3072*1024], g_wgl[(size_t)NLAYER*3072*1024];
__device__ __nv_bfloat16 g_wuh[(size_t)NLAYER*3072*1024], g_wul[(size_t)NLAYER*3072*1024];
__device__ __nv_bfloat16 g_wdh[(size_t)NLAYER*1024*3072], g_wdl[(size_t)NLAYER*1024*3072];
__device__ __nv_bfloat16 g_lmh[(size_t)VOC*1024],         g_lml[(size_t)VOC*1024];

// ------------------------- helpers -------------------------
__device__ __forceinline__ unsigned pack_hi(float x, float y, float& rx, float& ry) {
    __nv_bfloat16 bx = __float2bfloat16_rn(x);
    __nv_bfloat16 by = __float2bfloat16_rn(y);
    rx = x - __bfloat162float(bx);
    ry = y - __bfloat162float(by);
    return (unsigned)__bfloat16_as_ushort(bx) | ((unsigned)__bfloat16_as_ushort(by) << 16);
}
__device__ __forceinline__ unsigned pack_lo(float rx, float ry) {
    return (unsigned)__bfloat16_as_ushort(__float2bfloat16_rn(rx)) |
           ((unsigned)__bfloat16_as_ushort(__float2bfloat16_rn(ry)) << 16);
}
__device__ __forceinline__ unsigned s2u(const void* p) {
    return (unsigned)__cvta_generic_to_shared(p);
}

#define MMA_BF16(c, a, b) \
    asm volatile("mma.sync.aligned.m16n8k16.row.col.f32.bf16.bf16.f32 " \
                 "{%0,%1,%2,%3}, {%4,%5,%6,%7}, {%8,%9}, {%0,%1,%2,%3};\n" \
                 : "+f"(c[0]), "+f"(c[1]), "+f"(c[2]), "+f"(c[3]) \
                 : "r"(a[0]), "r"(a[1]), "r"(a[2]), "r"(a[3]), \
                   "r"(b[0]), "r"(b[1]))
#define LDSM4(r, a) \
    asm volatile("ldmatrix.sync.aligned.m8n8.x4.shared.b16 {%0,%1,%2,%3}, [%4];" \
                 : "=r"(r[0]), "=r"(r[1]), "=r"(r[2]), "=r"(r[3]) : "r"(a))
#define LDSM2(r, a) \
    asm volatile("ldmatrix.sync.aligned.m8n8.x2.shared.b16 {%0,%1}, [%2];" \
                 : "=r"(r[0]), "=r"(r[1]) : "r"(a))
#define CPA16(dst, src) \
    asm volatile("cp.async.cg.shared.global [%0], [%1], 16;\n" :: "r"(dst), "l"(src))
#define CPCOMMIT() asm volatile("cp.async.commit_group;\n" ::: "memory")
#define CPWAIT1()  asm volatile("cp.async.wait_group 1;\n" ::: "memory")

// smem tile: [stage][arr: Ah,Al,Bh,Bl][row 0..127][kpair 0..15 pad 20]
#define KP_STRIDE 20
#define ARR_WORDS (128*KP_STRIDE)          // 2560
#define SMEM_WORDS (2*4*ARR_WORDS)         // 20480 words = 81920 B

// ------------------------- rope tables -------------------------
__global__ void rope_table_kernel() {
    int pos = blockIdx.x;
    int j = threadIdx.x;
    double inv = pow(1.0e6, -((double)(2 * j)) / 128.0);
    double ang = (double)pos * inv;
    g_cos[pos * 64 + j] = (float)cos(ang);
    g_sin[pos * 64 + j] = (float)sin(ang);
}

// ------------------------- embedding gather -------------------------
__global__ void embed_kernel(const int* __restrict__ ids, const float* __restrict__ emb,
                             float* __restrict__ out) {
    int t = blockIdx.x;
    int id = ids[t];
    const float4* src = (const float4*)(emb + (size_t)id * H);
    float4* dst = (float4*)(out + (size_t)t * H);
    dst[threadIdx.x] = src[threadIdx.x];
}

// ------------------------- weight transpose + split: W[K][N] -> Wt[N][K] hi/lo ----
__global__ __launch_bounds__(256) void wsplit_kernel(const float* __restrict__ W,
                                                     __nv_bfloat16* __restrict__ Wh,
                                                     __nv_bfloat16* __restrict__ Wl,
                                                     int K, int N) {
    __shared__ float t[32][33];
    int n0 = blockIdx.x * 32, k0 = blockIdx.y * 32;
    int tx = threadIdx.x & 31, ty = threadIdx.x >> 5;   // 32 x 8
    #pragma unroll
    for (int i = 0; i < 4; i++)
        t[ty + 8*i][tx] = W[(size_t)(k0 + ty + 8*i) * N + n0 + tx];
    __syncthreads();
    #pragma unroll
    for (int i = 0; i < 4; i++) {
        float v = t[tx][ty + 8*i];
        __nv_bfloat16 hi = __float2bfloat16_rn(v);
        float lo = v - __bfloat162float(hi);
        size_t o = (size_t)(n0 + ty + 8*i) * K + k0 + tx;
        Wh[o] = hi;
        Wl[o] = __float2bfloat16_rn(lo);
    }
}

// ------------------------- rmsnorm over H=1024 -> packed hi/lo bf16 ----------
__global__ __launch_bounds__(256) void rmsnorm_kernel(const float* __restrict__ in,
                                                      const float* __restrict__ w,
                                                      unsigned* __restrict__ oh,
                                                      unsigned* __restrict__ ol) {
    int r = blockIdx.x, tid = threadIdx.x;
    const float4* ip = (const float4*)(in + (size_t)r * H);
    float4 v = ip[tid];
    float sq = v.x*v.x + v.y*v.y + v.z*v.z + v.w*v.w;
    __shared__ float red[8];
    __shared__ float s_scale;
    #pragma unroll
    for (int o = 16; o > 0; o >>= 1) sq += __shfl_xor_sync(0xffffffffu, sq, o);
    if ((tid & 31) == 0) red[tid >> 5] = sq;
    __syncthreads();
    if (tid == 0) {
        float t2 = 0.f;
        #pragma unroll
        for (int i = 0; i < 8; i++) t2 += red[i];
        s_scale = rsqrtf(t2 * (1.0f / H) + 1e-6f);
    }
    __syncthreads();
    float sc = s_scale;
    float4 wv = ((const float4*)w)[tid];
    float o0 = v.x * sc * wv.x, o1 = v.y * sc * wv.y;
    float o2 = v.z * sc * wv.z, o3 = v.w * sc * wv.w;
    float rx, ry;
    int base = r * (H/2) + tid * 2;
    unsigned h0 = pack_hi(o0, o1, rx, ry);
    ol[base] = pack_lo(rx, ry);
    oh[base] = h0;
    unsigned h1 = pack_hi(o2, o3, rx, ry);
    ol[base + 1] = pack_lo(rx, ry);
    oh[base + 1] = h1;
}

// ------------------------- per-head rmsnorm + rope (in place, fp32) ----------
__global__ __launch_bounds__(HD) void qknorm_rope_kernel(float* __restrict__ x,
                                                         const float* __restrict__ w,
                                                         int nheads) {
    int t = blockIdx.x;
    int hh = blockIdx.y;
    int d = threadIdx.x;
    float* p = x + ((size_t)t * nheads + hh) * HD;
    float val = p[d];
    float sq = val * val;
    #pragma unroll
    for (int o = 16; o > 0; o >>= 1) sq += __shfl_xor_sync(0xffffffffu, sq, o);
    __shared__ float red[4];
    __shared__ float sh[HD];
    if ((d & 31) == 0) red[d >> 5] = sq;
    __syncthreads();
    float tot = red[0] + red[1] + red[2] + red[3];
    float rms = rsqrtf(tot * (1.0f / HD) + 1e-6f);
    float xn = val * rms * w[d];
    sh[d] = xn;
    __syncthreads();
    int pos = t & (SEQ - 1);
    int j = d & 63;
    float c = g_cos[pos * 64 + j];
    float s = g_sin[pos * 64 + j];
    float out = (d < 64) ? (xn * c - sh[d + 64] * s)
                         : (xn * c + sh[d - 64] * s);
    p[d] = out;
}

// ------------------------- pipelined pure-bf16x3 GEMM --------------------------
// C (+)= Ahi/lo[M][K] @ (Bhi/lo[N][K])^T ; all operands pre-split bf16 (packed pairs).
__global__ __launch_bounds__(256, 2) void gemm_pre(const unsigned* __restrict__ Ah,
                                                   const unsigned* __restrict__ Al,
                                                   const unsigned* __restrict__ Bh,
                                                   const unsigned* __restrict__ Bl,
                                                   float* __restrict__ C,
                                                   int M, int N, int K, int accum) {
    extern __shared__ unsigned sm[];
    const int Kp = K >> 1;                       // pitch in packed pairs
    int tid = threadIdx.x;
    int bm = blockIdx.y * 128, bn = blockIdx.x * 128;
    int w = tid >> 5, lane = tid & 31, gid = lane >> 2, tg = lane & 3;
    int wm = (w >> 2) * 64, wn = (w & 3) * 32;
    unsigned sbase = s2u(sm);

    // cp.async fill assignment: 512 16B-chunks per array, 2 per thread per array
    int c0 = tid, c1 = tid + 256;
    int r0 = c0 >> 2, q0 = (c0 & 3) * 4;
    int r1 = c1 >> 2, q1 = (c1 & 3) * 4;

    // ldmatrix lane offsets
    int ra = lane & 15, kao = (lane >> 4) * 4;   // A x4
    int rb = lane & 7,  kbo = ((lane >> 3) & 1) * 4; // B x2

    float acc[4][4][4];
    #pragma unroll
    for (int mt = 0; mt < 4; mt++)
        #pragma unroll
        for (int nt = 0; nt < 4; nt++)
            #pragma unroll
            for (int r = 0; r < 4; r++) acc[mt][nt][r] = 0.f;

#define FILL(st, kp0) { \
    size_t a0 = (size_t)(bm + r0) * Kp + (kp0) + q0; \
    size_t a1 = (size_t)(bm + r1) * Kp + (kp0) + q1; \
    size_t b0 = (size_t)(bn + r0) * Kp + (kp0) + q0; \
    size_t b1 = (size_t)(bn + r1) * Kp + (kp0) + q1; \
    unsigned d_; \
    d_ = sbase + 4*(((st)*4 + 0)*ARR_WORDS + r0*KP_STRIDE + q0); CPA16(d_, Ah + a0); \
    d_ = sbase + 4*(((st)*4 + 0)*ARR_WORDS + r1*KP_STRIDE + q1); CPA16(d_, Ah + a1); \
    d_ = sbase + 4*(((st)*4 + 1)*ARR_WORDS + r0*KP_STRIDE + q0); CPA16(d_, Al + a0); \
    d_ = sbase + 4*(((st)*4 + 1)*ARR_WORDS + r1*KP_STRIDE + q1); CPA16(d_, Al + a1); \
    d_ = sbase + 4*(((st)*4 + 2)*ARR_WORDS + r0*KP_STRIDE + q0); CPA16(d_, Bh + b0); \
    d_ = sbase + 4*(((st)*4 + 2)*ARR_WORDS + r1*KP_STRIDE + q1); CPA16(d_, Bh + b1); \
    d_ = sbase + 4*(((st)*4 + 3)*ARR_WORDS + r0*KP_STRIDE + q0); CPA16(d_, Bl + b0); \
    d_ = sbase + 4*(((st)*4 + 3)*ARR_WORDS + r1*KP_STRIDE + q1); CPA16(d_, Bl + b1); \
}

    int nch = K / 32;
    FILL(0, 0);
    CPCOMMIT();
    for (int ch = 0; ch < nch; ch++) {
        int st = ch & 1;
        if (ch + 1 < nch) { FILL((ch + 1) & 1, (ch + 1) * 16); }
        CPCOMMIT();
        CPWAIT1();
        __syncthreads();
        #pragma unroll
        for (int s = 0; s < 2; s++) {
            unsigned bh[4][2], bl[4][2];
            #pragma unroll
            for (int nt = 0; nt < 4; nt++) {
                unsigned ab = sbase + 4*((st*4 + 2)*ARR_WORDS + (wn + nt*8 + rb)*KP_STRIDE + s*8 + kbo);
                LDSM2(bh[nt], ab);
                ab = sbase + 4*((st*4 + 3)*ARR_WORDS + (wn + nt*8 + rb)*KP_STRIDE + s*8 + kbo);
                LDSM2(bl[nt], ab);
            }
            #pragma unroll
            for (int mt = 0; mt < 4; mt++) {
                unsigned ah[4], al[4];
                unsigned aa = sbase + 4*((st*4 + 0)*ARR_WORDS + (wm + mt*16 + ra)*KP_STRIDE + s*8 + kao);
                LDSM4(ah, aa);
                aa = sbase + 4*((st*4 + 1)*ARR_WORDS + (wm + mt*16 + ra)*KP_STRIDE + s*8 + kao);
                LDSM4(al, aa);
                #pragma unroll
                for (int nt = 0; nt < 4; nt++) {
                    MMA_BF16(acc[mt][nt], ah, bh[nt]);
                    MMA_BF16(acc[mt][nt], ah, bl[nt]);
                    MMA_BF16(acc[mt][nt], al, bh[nt]);
                }
            }
        }
        __syncthreads();
    }
#undef FILL

    #pragma unroll
    for (int mt = 0; mt < 4; mt++) {
        #pragma unroll
        for (int nt = 0; nt < 4; nt++) {
            int row0 = bm + wm + mt * 16 + gid;
            int col = bn + wn + nt * 8 + tg * 2;
            float* Cp0 = C + (size_t)row0 * N + col;
            float* Cp1 = C + (size_t)(row0 + 8) * N + col;
            if (accum) {
                float2 o0 = *(float2*)Cp0;
                float2 o1 = *(float2*)Cp1;
                *(float2*)Cp0 = make_float2(o0.x + acc[mt][nt][0], o0.y + acc[mt][nt][1]);
                *(float2*)Cp1 = make_float2(o1.x + acc[mt][nt][2], o1.y + acc[mt][nt][3]);
            } else {
                *(float2*)Cp0 = make_float2(acc[mt][nt][0], acc[mt][nt][1]);
                *(float2*)Cp1 = make_float2(acc[mt][nt][2], acc[mt][nt][3]);
            }
        }
    }
}

// ------------------------- bf16x3 split-at-fill attention kernels -------------
#define MMA_CHUNK_BODY(Ah, Al, Bh, Bl, acc, wm, wn, gid, tg)                    \
    _Pragma("unroll")                                                           \
    for (int s = 0; s < 2; s++) {                                               \
        int kb = s * 8;                                                         \
        unsigned bh[4][2], bl[4][2];                                            \
        _Pragma("unroll")                                                       \
        for (int nt = 0; nt < 4; nt++) {                                        \
            int n = wn + nt * 8 + gid;                                          \
            bh[nt][0] = Bh[n][kb + tg];  bh[nt][1] = Bh[n][kb + tg + 4];        \
            bl[nt][0] = Bl[n][kb + tg];  bl[nt][1] = Bl[n][kb + tg + 4];        \
        }                                                                       \
        _Pragma("unroll")                                                       \
        for (int mt = 0; mt < 4; mt++) {                                        \
            int m0 = wm + mt * 16 + gid;                                        \
            unsigned ah[4], al[4];                                              \
            ah[0] = Ah[m0][kb + tg];      ah[1] = Ah[m0 + 8][kb + tg];          \
            ah[2] = Ah[m0][kb + tg + 4];  ah[3] = Ah[m0 + 8][kb + tg + 4];      \
            al[0] = Al[m0][kb + tg];      al[1] = Al[m0 + 8][kb + tg];          \
            al[2] = Al[m0][kb + tg + 4];  al[3] = Al[m0 + 8][kb + tg + 4];      \
            _Pragma("unroll")                                                   \
            for (int nt = 0; nt < 4; nt++) {                                    \
                MMA_BF16(acc[mt][nt], ah, bh[nt]);                              \
                MMA_BF16(acc[mt][nt], ah, bl[nt]);                              \
                MMA_BF16(acc[mt][nt], al, bh[nt]);                              \
            }                                                                   \
        }                                                                       \
    }

__global__ __launch_bounds__(256, 2) void attn_scores_mma(const float* __restrict__ q,
                                                          const float* __restrict__ k,
                                                          float* __restrict__ sc) {
    int z = blockIdx.z, b = z >> 4, h = z & 15;
    int i0 = blockIdx.y * 128, j0 = blockIdx.x * 128;
    if (j0 > i0) return;
    __shared__ unsigned Ah[128][KP_STRIDE], Al[128][KP_STRIDE];
    __shared__ unsigned Bh[128][KP_STRIDE], Bl[128][KP_STRIDE];
    int tid = threadIdx.x;
    int w = tid >> 5, lane = tid & 31, gid = lane >> 2, tg = lane & 3;
    int wm = (w >> 2) * 64, wn = (w & 3) * 32;
    int arow = tid >> 1, ak0 = (tid & 1) * 8;

    const float* Ag = q + ((size_t)b * SEQ * NH + h) * HD + (size_t)(i0 + arow) * (NH * HD) + ak0 * 2;
    const float* Bg = k + ((size_t)b * SEQ * NKV + (h >> 1)) * HD + (size_t)(j0 + arow) * (NKV * HD) + ak0 * 2;

    float acc[4][4][4];
    #pragma unroll
    for (int mt = 0; mt < 4; mt++)
        #pragma unroll
        for (int nt = 0; nt < 4; nt++)
            #pragma unroll
            for (int r = 0; r < 4; r++) acc[mt][nt][r] = 0.f;

    for (int d0 = 0; d0 < HD; d0 += 32) {
        #pragma unroll
        for (int qq = 0; qq < 4; qq++) {
            float4 v = *(const float4*)(Ag + d0 + qq * 4);
            float rx, ry;
            Ah[arow][ak0 + qq*2    ] = pack_hi(v.x, v.y, rx, ry);
            Al[arow][ak0 + qq*2    ] = pack_lo(rx, ry);
            Ah[arow][ak0 + qq*2 + 1] = pack_hi(v.z, v.w, rx, ry);
            Al[arow][ak0 + qq*2 + 1] = pack_lo(rx, ry);
            float4 u = *(const float4*)(Bg + d0 + qq * 4);
            Bh[arow][ak0 + qq*2    ] = pack_hi(u.x, u.y, rx, ry);
            Bl[arow][ak0 + qq*2    ] = pack_lo(rx, ry);
            Bh[arow][ak0 + qq*2 + 1] = pack_hi(u.z, u.w, rx, ry);
            Bl[arow][ak0 + qq*2 + 1] = pack_lo(rx, ry);
        }
        __syncthreads();
        MMA_CHUNK_BODY(Ah, Al, Bh, Bl, acc, wm, wn, gid, tg)
        __syncthreads();
    }

    const float scale = 0.08838834764831845f;
    size_t zoff = (size_t)z * SEQ * SEQ;
    #pragma unroll
    for (int mt = 0; mt < 4; mt++) {
        #pragma unroll
        for (int nt = 0; nt < 4; nt++) {
            int row0 = i0 + wm + mt * 16 + gid;
            int col = j0 + wn + nt * 8 + tg * 2;
            *(float2*)(sc + zoff + (size_t)row0 * SEQ + col) =
                make_float2(acc[mt][nt][0] * scale, acc[mt][nt][1] * scale);
            *(float2*)(sc + zoff + (size_t)(row0 + 8) * SEQ + col) =
                make_float2(acc[mt][nt][2] * scale, acc[mt][nt][3] * scale);
        }
    }
}

__global__ __launch_bounds__(256) void softmax_kernel(float* __restrict__ sc) {
    int i = blockIdx.x;
    int z = blockIdx.y;
    float* row = sc + (size_t)z * SEQ * SEQ + (size_t)i * SEQ;
    int len = i + 1;
    int tid = threadIdx.x;
    __shared__ float red[8];
    float m = -1e30f;
    for (int j = tid; j < len; j += 256) m = fmaxf(m, row[j]);
    #pragma unroll
    for (int o = 16; o > 0; o >>= 1) m = fmaxf(m, __shfl_xor_sync(0xffffffffu, m, o));
    if ((tid & 31) == 0) red[tid >> 5] = m;
    __syncthreads();
    if (tid == 0) {
        float t = red[0];
        #pragma unroll
        for (int w = 1; w < 8; w++) t = fmaxf(t, red[w]);
        red[0] = t;
    }
    __syncthreads();
    float bm = red[0];
    __syncthreads();
    float s = 0.f;
    for (int j = tid; j < len; j += 256) s += __expf(row[j] - bm);
    #pragma unroll
    for (int o = 16; o > 0; o >>= 1) s += __shfl_xor_sync(0xffffffffu, s, o);
    if ((tid & 31) == 0) red[tid >> 5] = s;
    __syncthreads();
    if (tid == 0) {
        float t = 0.f;
        #pragma unroll
        for (int w = 0; w < 8; w++) t += red[w];
        red[0] = 1.0f / t;
    }
    __syncthreads();
    float inv = red[0];
    for (int j = tid; j < SEQ; j += 256)
        row[j] = (j < len) ? __expf(row[j] - bm) * inv : 0.f;
}

// ctx = P @ V ; epilogue emits packed hi/lo bf16 for the Wo GEMM.
__global__ __launch_bounds__(256, 2) void attn_ctx_mma(const float* __restrict__ P,
                                                       const float* __restrict__ v,
                                                       unsigned* __restrict__ ctxh,
                                                       unsigned* __restrict__ ctxl) {
    int z = blockIdx.y, b = z >> 4, h = z & 15;
    int i0 = blockIdx.x * 128;
    __shared__ unsigned Ah[128][KP_STRIDE], Al[128][KP_STRIDE];
    __shared__ unsigned Bh[128][KP_STRIDE], Bl[128][KP_STRIDE];
    int tid = threadIdx.x;
    int w = tid >> 5, lane = tid & 31, gid = lane >> 2, tg = lane & 3;
    int wm = (w >> 2) * 64, wn = (w & 3) * 32;
    int arow = tid >> 1, ak0 = (tid & 1) * 8;
    int bnn = tid & 127, bk0 = (tid >> 7) * 8;

    const float* Pb = P + (size_t)z * SEQ * SEQ + (size_t)(i0 + arow) * SEQ + ak0 * 2;
    const float* vb = v + ((size_t)b * SEQ * NKV + (h >> 1)) * HD + bnn;

    float acc[4][4][4];
    #pragma unroll
    for (int mt = 0; mt < 4; mt++)
        #pragma unroll
        for (int nt = 0; nt < 4; nt++)
            #pragma unroll
            for (int r = 0; r < 4; r++) acc[mt][nt][r] = 0.f;

    int jmax = i0 + 128;
    for (int k0 = 0; k0 < jmax; k0 += 32) {
        #pragma unroll
        for (int q = 0; q < 4; q++) {
            float4 pv = *(const float4*)(Pb + k0 + q * 4);
            float rx, ry;
            Ah[arow][ak0 + q*2    ] = pack_hi(pv.x, pv.y, rx, ry);
            Al[arow][ak0 + q*2    ] = pack_lo(rx, ry);
            Ah[arow][ak0 + q*2 + 1] = pack_hi(pv.z, pv.w, rx, ry);
            Al[arow][ak0 + q*2 + 1] = pack_lo(rx, ry);
        }
        #pragma unroll
        for (int i = 0; i < 8; i++) {
            float x = vb[(size_t)(k0 + bk0*2 + 2*i    ) * (NKV * HD)];
            float y = vb[(size_t)(k0 + bk0*2 + 2*i + 1) * (NKV * HD)];
            float rx, ry;
            Bh[bnn][bk0 + i] = pack_hi(x, y, rx, ry);
            Bl[bnn][bk0 + i] = pack_lo(rx, ry);
        }
        __syncthreads();
        MMA_CHUNK_BODY(Ah, Al, Bh, Bl, acc, wm, wn, gid, tg)
        __syncthreads();
    }

    #pragma unroll
    for (int mt = 0; mt < 4; mt++) {
        #pragma unroll
        for (int nt = 0; nt < 4; nt++) {
            int row0 = i0 + wm + mt * 16 + gid;
            int col = wn + nt * 8 + tg * 2;
            size_t base0 = (((size_t)(b * SEQ + row0)) * NH + h) * HD + col;
            size_t base1 = (((size_t)(b * SEQ + row0 + 8)) * NH + h) * HD + col;
            float rx, ry;
            unsigned h0 = pack_hi(acc[mt][nt][0], acc[mt][nt][1], rx, ry);
            ctxh[base0 >> 1] = h0;
            ctxl[base0 >> 1] = pack_lo(rx, ry);
            unsigned h1 = pack_hi(acc[mt][nt][2], acc[mt][nt][3], rx, ry);
            ctxh[base1 >> 1] = h1;
            ctxl[base1 >> 1] = pack_lo(rx, ry);
        }
    }
}

// ------------------------- fused SiLU(gate) * up -> packed hi/lo ----------
__global__ void silu_mul_kernel(const float* __restrict__ g, const float* __restrict__ u,
                                unsigned* __restrict__ oh, unsigned* __restrict__ ol, int n2) {
    int i = blockIdx.x * blockDim.x + threadIdx.x;
    if (i < n2) {
        float x0 = g[2*i], x1 = g[2*i + 1];
        float y0 = x0 / (1.0f + __expf(-x0)) * u[2*i];
        float y1 = x1 / (1.0f + __expf(-x1)) * u[2*i + 1];
        float rx, ry;
        unsigned hh = pack_hi(y0, y1, rx, ry);
        oh[i] = hh;
        ol[i] = pack_lo(rx, ry);
    }
}

// ------------------------- host orchestration -------------------------
extern "C" void kernel_launch(void* const* d_in, const int* in_sizes, int n_in,
                              void* d_out, int out_size) {
    const int*   ids     = (const int*)d_in[0];
    const float* embed   = (const float*)d_in[1];
    const float* Wq      = (const float*)d_in[2];
    const float* Wk      = (const float*)d_in[3];
    const float* Wv      = (const float*)d_in[4];
    const float* Wo      = (const float*)d_in[5];
    const float* qn      = (const float*)d_in[6];
    const float* kn      = (const float*)d_in[7];
    const float* ln1     = (const float*)d_in[8];
    const float* ln2     = (const float*)d_in[9];
    const float* Wg      = (const float*)d_in[10];
    const float* Wu      = (const float*)d_in[11];
    const float* Wd      = (const float*)d_in[12];
    const float* norm_w  = (const float*)d_in[13];
    const float* lm_head = (const float*)d_in[14];
    float* out = (float*)d_out;
    (void)in_sizes; (void)n_in; (void)out_size;

    static int smem_set = 0;
    if (!smem_set) {
        cudaFuncSetAttribute(gemm_pre, cudaFuncAttributeMaxDynamicSharedMemorySize, SMEM_WORDS * 4);
        smem_set = 1;
    }

    float *ph, *pq, *pk, *pv, *psc, *pg, *pu;
    cudaGetSymbolAddress((void**)&ph,  g_h);
    cudaGetSymbolAddress((void**)&pq,  g_q);
    cudaGetSymbolAddress((void**)&pk,  g_k);
    cudaGetSymbolAddress((void**)&pv,  g_v);
    cudaGetSymbolAddress((void**)&psc, g_sc);
    cudaGetSymbolAddress((void**)&pg,  g_gate);
    cudaGetSymbolAddress((void**)&pu,  g_up);
    unsigned *pxh, *pxl, *pch, *pcl, *pgh, *pgl;
    cudaGetSymbolAddress((void**)&pxh, g_xh);
    cudaGetSymbolAddress((void**)&pxl, g_xl);
    cudaGetSymbolAddress((void**)&pch, g_ctxh);
    cudaGetSymbolAddress((void**)&pcl, g_ctxl);
    cudaGetSymbolAddress((void**)&pgh, g_gh);
    cudaGetSymbolAddress((void**)&pgl, g_gl);
    __nv_bfloat16 *wqh, *wql, *wkh, *wkl, *wvh, *wvl, *woh, *wol;
    __nv_bfloat16 *wgh, *wgl, *wuh, *wul, *wdh, *wdl, *lmh, *lml;
    cudaGetSymbolAddress((void**)&wqh, g_wqh); cudaGetSymbolAddress((void**)&wql, g_wql);
    cudaGetSymbolAddress((void**)&wkh, g_wkh); cudaGetSymbolAddress((void**)&wkl, g_wkl);
    cudaGetSymbolAddress((void**)&wvh, g_wvh); cudaGetSymbolAddress((void**)&wvl, g_wvl);
    cudaGetSymbolAddress((void**)&woh, g_woh); cudaGetSymbolAddress((void**)&wol, g_wol);
    cudaGetSymbolAddress((void**)&wgh, g_wgh); cudaGetSymbolAddress((void**)&wgl, g_wgl);
    cudaGetSymbolAddress((void**)&wuh, g_wuh); cudaGetSymbolAddress((void**)&wul, g_wul);
    cudaGetSymbolAddress((void**)&wdh, g_wdh); cudaGetSymbolAddress((void**)&wdl, g_wdl);
    cudaGetSymbolAddress((void**)&lmh, g_lmh); cudaGetSymbolAddress((void**)&lml, g_lml);

    // --- pre-split all weights (transposed [N][K] hi/lo bf16) ---
    for (int l = 0; l < NLAYER; l++) {
        wsplit_kernel<<<dim3(2048/32, 1024/32), 256>>>(Wq + (size_t)l*1024*2048, wqh + (size_t)l*2048*1024, wql + (size_t)l*2048*1024, 1024, 2048);
        wsplit_kernel<<<dim3(1024/32, 1024/32), 256>>>(Wk + (size_t)l*1024*1024, wkh + (size_t)l*1024*1024, wkl + (size_t)l*1024*1024, 1024, 1024);
        wsplit_kernel<<<dim3(1024/32, 1024/32), 256>>>(Wv + (size_t)l*1024*1024, wvh + (size_t)l*1024*1024, wvl + (size_t)l*1024*1024, 1024, 1024);
        wsplit_kernel<<<dim3(1024/32, 2048/32), 256>>>(Wo + (size_t)l*2048*1024, woh + (size_t)l*1024*2048, wol + (size_t)l*1024*2048, 2048, 1024);
        wsplit_kernel<<<dim3(3072/32, 1024/32), 256>>>(Wg + (size_t)l*1024*3072, wgh + (size_t)l*3072*1024, wgl + (size_t)l*3072*1024, 1024, 3072);
        wsplit_kernel<<<dim3(3072/32, 1024/32), 256>>>(Wu + (size_t)l*1024*3072, wuh + (size_t)l*3072*1024, wul + (size_t)l*3072*1024, 1024, 3072);
        wsplit_kernel<<<dim3(1024/32, 3072/32), 256>>>(Wd + (size_t)l*3072*1024, wdh + (size_t)l*1024*3072, wdl + (size_t)l*1024*3072, 3072, 1024);
    }
    wsplit_kernel<<<dim3(VOC/32, 1024/32), 256>>>(lm_head, lmh, lml, 1024, VOC);

    rope_table_kernel<<<SEQ, 64>>>();
    embed_kernel<<<T, 256>>>(ids, embed, ph);

    const int SMB = SMEM_WORDS * 4;
    for (int l = 0; l < NLAYER; l++) {
        rmsnorm_kernel<<<T, 256>>>(ph, ln1 + (size_t)l * H, pxh, pxl);

        gemm_pre<<<dim3(2048/128, T/128), 256, SMB>>>(pxh, pxl, (const unsigned*)(wqh + (size_t)l*2048*1024), (const unsigned*)(wql + (size_t)l*2048*1024), pq, T, 2048, 1024, 0);
        gemm_pre<<<dim3(1024/128, T/128), 256, SMB>>>(pxh, pxl, (const unsigned*)(wkh + (size_t)l*1024*1024), (const unsigned*)(wkl + (size_t)l*1024*1024), pk, T, 1024, 1024, 0);
        gemm_pre<<<dim3(1024/128, T/128), 256, SMB>>>(pxh, pxl, (const unsigned*)(wvh + (size_t)l*1024*1024), (const unsigned*)(wvl + (size_t)l*1024*1024), pv, T, 1024, 1024, 0);

        qknorm_rope_kernel<<<dim3(T, NH), HD>>>(pq, qn + (size_t)l * HD, NH);
        qknorm_rope_kernel<<<dim3(T, NKV), HD>>>(pk, kn + (size_t)l * HD, NKV);

        attn_scores_mma<<<dim3(SEQ/128, SEQ/128, BATCH*NH), 256>>>(pq, pk, psc);
        softmax_kernel<<<dim3(SEQ, BATCH*NH), 256>>>(psc);
        attn_ctx_mma<<<dim3(SEQ/128, BATCH*NH), 256>>>(psc, pv, pch, pcl);

        gemm_pre<<<dim3(1024/128, T/128), 256, SMB>>>(pch, pcl, (const unsigned*)(woh + (size_t)l*1024*2048), (const unsigned*)(wol + (size_t)l*1024*2048), ph, T, 1024, 2048, 1);

        rmsnorm_kernel<<<T, 256>>>(ph, ln2 + (size_t)l * H, pxh, pxl);
        gemm_pre<<<dim3(3072/128, T/128), 256, SMB>>>(pxh, pxl, (const unsigned*)(wgh + (size_t)l*3072*1024), (const unsigned*)(wgl + (size_t)l*3072*1024), pg, T, 3072, 1024, 0);
        gemm_pre<<<dim3(3072/128, T/128), 256, SMB>>>(pxh, pxl, (const unsigned*)(wuh + (size_t)l*3072*1024), (const unsigned*)(wul + (size_t)l*3072*1024), pu, T, 3072, 1024, 0);
        silu_mul_kernel<<<(T*FFI/2 + 255)/256, 256>>>(pg, pu, pgh, pgl, T*FFI/2);
        gemm_pre<<<dim3(1024/128, T/128), 256, SMB>>>(pgh, pgl, (const unsigned*)(wdh + (size_t)l*1024*3072), (const unsigned*)(wdl + (size_t)l*1024*3072), ph, T, 1024, 3072, 1);
    }

    rmsnorm_kernel<<<T, 256>>>(ph, norm_w, pxh, pxl);
    gemm_pre<<<dim3(VOC/128, T/128), 256, SMB>>>(pxh, pxl, (const unsigned*)lmh, (const unsigned*)lml, out, T, VOC, 1024, 0);
}